// round 11
// baseline (speedup 1.0000x reference)
#include <cuda_runtime.h>
#include <math.h>
#include <stdint.h>

#define Bq   8
#define Nn   3136
#define C1d  64
#define C2d  128
#define KVd  192
#define Hh   4
#define MLPd 256
#define NROW (Bq*Nn)     /* 25088 */
#define NCH  49          /* 3136 / 64 */
#define GSZ  (C1d*KVd)   /* 12288 */

// ---------------- scratch (device globals; no allocation) ----------------
__device__ float g_ea[NROW*KVd];          // LN(concat) rows (fp32; mma truncates)
__device__ float g_G[Bq*GSZ];             // fp32 atomic-accumulated G
__device__ float g_S[Bq*Hh*GSZ];          // scores (scaled, pre-IN, fp32)
__device__ float2 g_pstats[Bq*Hh*4];      // per-tile (sum, sumsq) of scores
__device__ float g_Pp[Bq*Hh*GSZ];         // probs @ Wv (fp32)
__device__ float g_M[Bq*GSZ];             // M

extern __shared__ float dsm[];

__device__ __forceinline__ uint32_t bits(float f) { return __float_as_uint(f); }
// mma reads the top 19 bits of each operand -> fp32 bits act as RZ-truncated tf32
__device__ __forceinline__ void mma_tf32(float* c, const uint32_t* a, const uint32_t* b) {
    asm volatile("mma.sync.aligned.m16n8k8.row.col.f32.tf32.tf32.f32 "
        "{%0,%1,%2,%3}, {%4,%5,%6,%7}, {%8,%9}, {%0,%1,%2,%3};"
        : "+f"(c[0]), "+f"(c[1]), "+f"(c[2]), "+f"(c[3])
        : "r"(a[0]), "r"(a[1]), "r"(a[2]), "r"(a[3]), "r"(b[0]), "r"(b[1]));
}

// ============ 0) init: zero g_G ============
__global__ void init_kernel() {
    g_G[blockIdx.x*256 + threadIdx.x] = 0.f;
}

// ============ 1) fused dual-LayerNorm + G partial -> atomicAdd into g_G =====
// grid (49, 8), 256 threads
__global__ __launch_bounds__(256,2) void gmatln_kernel(
        const float* __restrict__ emb1, const float* __restrict__ emb2,
        const float* __restrict__ g1, const float* __restrict__ b1,
        const float* __restrict__ gA, const float* __restrict__ bA) {
    float* sE = dsm;                 // [64][196] raw -> ea
    float* sC = dsm + 64*196;        // [64][65]  cx1
    __shared__ float m1s[64], r1s[64], mAs[64], rAs[64];
    int ch = blockIdx.x, b = blockIdx.y;
    int base = b*Nn + ch*64;
    int tid = threadIdx.x;
    for (int i = tid; i < 64*48; i += 256) {
        int r = i / 48, c = (i % 48)*4;
        float4 v = (c < C1d) ? *(const float4*)(emb1 + (size_t)(base+r)*C1d + c)
                             : *(const float4*)(emb2 + (size_t)(base+r)*C2d + (c - C1d));
        *(float4*)(sE + r*196 + c) = v;
    }
    __syncthreads();
    if (tid < 64) {
        float s1 = 0.f, q1 = 0.f, s2 = 0.f, q2 = 0.f;
        const float* row = sE + tid*196;
        #pragma unroll 8
        for (int c = 0; c < C1d; c++)  { float v = row[c]; s1 += v; q1 += v*v; }
        #pragma unroll 8
        for (int c = C1d; c < KVd; c++){ float v = row[c]; s2 += v; q2 += v*v; }
        float m1 = s1 * (1.f/C1d);
        float v1 = q1 * (1.f/C1d) - m1*m1;
        m1s[tid] = m1; r1s[tid] = rsqrtf(v1 + 1e-6f);
        float mA = (s1+s2) * (1.f/KVd);
        float vA = (q1+q2) * (1.f/KVd) - mA*mA;
        mAs[tid] = mA; rAs[tid] = rsqrtf(vA + 1e-6f);
    }
    __syncthreads();
    for (int i = tid; i < 64*48; i += 256) {
        int r = i / 48, c = (i % 48)*4;
        float4 v = *(const float4*)(sE + r*196 + c);
        float4 g = *(const float4*)(gA + c);
        float4 bb4 = *(const float4*)(bA + c);
        float mA = mAs[r], rA = rAs[r];
        float4 ea;
        ea.x = (v.x - mA)*rA*g.x + bb4.x;
        ea.y = (v.y - mA)*rA*g.y + bb4.y;
        ea.z = (v.z - mA)*rA*g.z + bb4.z;
        ea.w = (v.w - mA)*rA*g.w + bb4.w;
        *(float4*)(sE + r*196 + c) = ea;
        *(float4*)(g_ea + (size_t)(base+r)*KVd + c) = ea;
        if (c < C1d) {
            float m1 = m1s[r], r1 = r1s[r];
            sC[r*65 + c+0] = (v.x - m1)*r1*__ldg(g1 + c+0) + __ldg(b1 + c+0);
            sC[r*65 + c+1] = (v.y - m1)*r1*__ldg(g1 + c+1) + __ldg(b1 + c+1);
            sC[r*65 + c+2] = (v.z - m1)*r1*__ldg(g1 + c+2) + __ldg(b1 + c+2);
            sC[r*65 + c+3] = (v.w - m1)*r1*__ldg(g1 + c+3) + __ldg(b1 + c+3);
        }
    }
    __syncthreads();
    int w = tid >> 5, lane = tid & 31;
    int gid = lane >> 2, tig = lane & 3;
    int wr = w >> 2, wc = w & 3;       // 2 x 4 warps; tile 32m x 48n
    float cacc[2][6][4];
    #pragma unroll
    for (int i = 0; i < 2; i++)
        #pragma unroll
        for (int j = 0; j < 6; j++)
            #pragma unroll
            for (int q = 0; q < 4; q++) cacc[i][j][q] = 0.f;
    for (int ks = 0; ks < C1d; ks += 8) {
        uint32_t a[2][4], bb[6][2];
        #pragma unroll
        for (int i = 0; i < 2; i++) {
            int m0 = wr*32 + i*16;
            a[i][0] = bits(sC[(ks+tig)*65 + m0+gid]);
            a[i][1] = bits(sC[(ks+tig)*65 + m0+8+gid]);
            a[i][2] = bits(sC[(ks+tig+4)*65 + m0+gid]);
            a[i][3] = bits(sC[(ks+tig+4)*65 + m0+8+gid]);
        }
        #pragma unroll
        for (int j = 0; j < 6; j++) {
            int n0 = wc*48 + j*8;
            bb[j][0] = bits(sE[(ks+tig)*196 + n0+gid]);
            bb[j][1] = bits(sE[(ks+tig+4)*196 + n0+gid]);
        }
        #pragma unroll
        for (int i = 0; i < 2; i++)
            #pragma unroll
            for (int j = 0; j < 6; j++)
                mma_tf32(cacc[i][j], a[i], bb[j]);
    }
    float* out = g_G + (size_t)b*GSZ;
    #pragma unroll
    for (int i = 0; i < 2; i++) {
        int r_lo = wr*32 + i*16 + gid, r_hi = r_lo + 8;
        #pragma unroll
        for (int j = 0; j < 6; j++) {
            int c0 = wc*48 + j*8 + 2*tig;
            atomicAdd(out + r_lo*KVd + c0,     cacc[i][j][0]);
            atomicAdd(out + r_lo*KVd + c0 + 1, cacc[i][j][1]);
            atomicAdd(out + r_hi*KVd + c0,     cacc[i][j][2]);
            atomicAdd(out + r_hi*KVd + c0 + 1, cacc[i][j][3]);
        }
    }
}

// ============ 2) fused T=Wq@G, S = T@Wk^T/sqrt(KV) + partial stats =====
// grid (32, 4), 384 threads (12 warps)
__global__ __launch_bounds__(384,1) void smatT_kernel(
        const float* __restrict__ Wq, const float* __restrict__ Wk) {
    float* sG  = dsm;                  // [64][196]
    float* sT  = dsm + 64*196;         // [64][196]
    float* sWq = sT + 64*196;          // [64][68]   Wq row-major
    float* sWk = sWq + 64*68;          // [192][52]  Wk^T tile
    __shared__ float redS[12], redQ[12];
    int bh = blockIdx.x, tile = blockIdx.y;
    int b = bh >> 2, h = bh & 3;
    int tid = threadIdx.x;
    for (int i = tid; i < 64*48; i += 384) {
        int c = i / 48, k = (i % 48)*4;
        *(float4*)(sG + c*196 + k) = *(const float4*)(g_G + (size_t)b*GSZ + c*KVd + k);
    }
    for (int i = tid; i < 1024; i += 384) {
        int d = i >> 4, c = (i & 15)*4;
        *(float4*)(sWq + d*68 + c) = *(const float4*)(Wq + (size_t)h*C1d*C1d + d*C1d + c);
    }
    for (int i = tid; i < 48*48; i += 384) {
        int j = i / 48, kp = (i % 48)*4;
        float4 v = *(const float4*)(Wk + (size_t)h*KVd*KVd + (tile*48 + j)*KVd + kp);
        sWk[(kp+0)*52 + j] = v.x;
        sWk[(kp+1)*52 + j] = v.y;
        sWk[(kp+2)*52 + j] = v.z;
        sWk[(kp+3)*52 + j] = v.w;
    }
    __syncthreads();
    int w = tid >> 5, lane = tid & 31;
    int gid = lane >> 2, tig = lane & 3;
    int wr = w & 3, wc = w >> 2;       // 4m x 3n warps
    // Phase 1: T = Wq @ G  (m=64, n=192, k=64); warp tile 16m x 64n
    {
        int m0 = wr*16;
        float cacc[8][4];
        #pragma unroll
        for (int j = 0; j < 8; j++)
            #pragma unroll
            for (int q = 0; q < 4; q++) cacc[j][q] = 0.f;
        for (int ks = 0; ks < C1d; ks += 8) {
            uint32_t a[4], bb[8][2];
            a[0] = bits(sWq[(m0+gid)*68 + ks+tig]);
            a[1] = bits(sWq[(m0+8+gid)*68 + ks+tig]);
            a[2] = bits(sWq[(m0+gid)*68 + ks+tig+4]);
            a[3] = bits(sWq[(m0+8+gid)*68 + ks+tig+4]);
            #pragma unroll
            for (int j = 0; j < 8; j++) {
                int n0 = wc*64 + j*8;
                bb[j][0] = bits(sG[(ks+tig)*196 + n0+gid]);
                bb[j][1] = bits(sG[(ks+tig+4)*196 + n0+gid]);
            }
            #pragma unroll
            for (int j = 0; j < 8; j++)
                mma_tf32(cacc[j], a, bb[j]);
        }
        int r_lo = m0 + gid, r_hi = r_lo + 8;
        #pragma unroll
        for (int j = 0; j < 8; j++) {
            int c0 = wc*64 + j*8 + 2*tig;
            *(float2*)(sT + r_lo*196 + c0) = make_float2(cacc[j][0], cacc[j][1]);
            *(float2*)(sT + r_hi*196 + c0) = make_float2(cacc[j][2], cacc[j][3]);
        }
    }
    __syncthreads();
    // Phase 2: S = T @ Wk^T * scale  (m=64, n=48, k=192); warp tile 16m x 16n
    const float scale = 0.0721687836487f;   // 1/sqrt(192)
    float lsum = 0.f, lsq = 0.f;
    {
        int m0 = wr*16, n0 = wc*16;
        float cacc[2][4];
        #pragma unroll
        for (int j = 0; j < 2; j++)
            #pragma unroll
            for (int q = 0; q < 4; q++) cacc[j][q] = 0.f;
        for (int ks = 0; ks < KVd; ks += 8) {
            uint32_t a[4], bb[2][2];
            a[0] = bits(sT[(m0+gid)*196 + ks+tig]);
            a[1] = bits(sT[(m0+8+gid)*196 + ks+tig]);
            a[2] = bits(sT[(m0+gid)*196 + ks+tig+4]);
            a[3] = bits(sT[(m0+8+gid)*196 + ks+tig+4]);
            #pragma unroll
            for (int j = 0; j < 2; j++) {
                int c0 = n0 + j*8;
                bb[j][0] = bits(sWk[(ks+tig)*52 + c0+gid]);
                bb[j][1] = bits(sWk[(ks+tig+4)*52 + c0+gid]);
            }
            #pragma unroll
            for (int j = 0; j < 2; j++)
                mma_tf32(cacc[j], a, bb[j]);
        }
        float* out = g_S + (size_t)bh*GSZ;
        int r_lo = m0 + gid, r_hi = r_lo + 8;
        #pragma unroll
        for (int j = 0; j < 2; j++) {
            int c0 = tile*48 + n0 + j*8 + 2*tig;
            float v0 = cacc[j][0]*scale, v1 = cacc[j][1]*scale;
            float v2 = cacc[j][2]*scale, v3 = cacc[j][3]*scale;
            *(float2*)(out + r_lo*KVd + c0) = make_float2(v0, v1);
            *(float2*)(out + r_hi*KVd + c0) = make_float2(v2, v3);
            lsum += v0+v1+v2+v3;
            lsq  += v0*v0+v1*v1+v2*v2+v3*v3;
        }
    }
    #pragma unroll
    for (int o = 16; o > 0; o >>= 1) {
        lsum += __shfl_down_sync(0xffffffffu, lsum, o);
        lsq  += __shfl_down_sync(0xffffffffu, lsq, o);
    }
    if (lane == 0) { redS[w] = lsum; redQ[w] = lsq; }
    __syncthreads();
    if (tid == 0) {
        float s = 0.f, q = 0.f;
        #pragma unroll
        for (int i = 0; i < 12; i++) { s += redS[i]; q += redQ[i]; }
        g_pstats[bh*4 + tile] = make_float2(s, q);
    }
}

// ============ 3) fused IN + softmax + Pp = probs @ Wv ========
// grid (32, 4), 384 threads (12 warps)
__global__ __launch_bounds__(384,2) void pmat_kernel(const float* __restrict__ Wv) {
    float* sS = dsm;                   // [64][196] scores -> probs
    float* sV = dsm + 64*196;          // [192][52] Wv tile
    __shared__ float s_m, s_rs;
    int bh = blockIdx.x, h = bh & 3, tile = blockIdx.y;
    int tid = threadIdx.x;
    for (int i = tid; i < 64*48; i += 384) {
        int c = i / 48, k = (i % 48)*4;
        *(float4*)(sS + c*196 + k) = *(const float4*)(g_S + (size_t)bh*GSZ + c*KVd + k);
    }
    for (int i = tid; i < 192*12; i += 384) {
        int k = i / 12, c = (i % 12)*4;
        *(float4*)(sV + k*52 + c) = *(const float4*)(Wv + (size_t)h*KVd*KVd + k*KVd + tile*48 + c);
    }
    if (tid == 0) {
        float s = 0.f, q = 0.f;
        #pragma unroll
        for (int t = 0; t < 4; t++) {
            float2 p = g_pstats[bh*4 + t];
            s += p.x; q += p.y;
        }
        float m = s * (1.f/GSZ);
        float v = q * (1.f/GSZ) - m*m;
        s_m = m; s_rs = rsqrtf(v + 1e-5f);
    }
    __syncthreads();
    float mean = s_m, rs = s_rs;
    int w = tid >> 5, lane = tid & 31;
    for (int r = w; r < C1d; r += 12) {
        float vals[6];
        float mx = -1e30f;
        #pragma unroll
        for (int mm = 0; mm < 6; mm++) {
            vals[mm] = (sS[r*196 + lane + 32*mm] - mean) * rs;
            mx = fmaxf(mx, vals[mm]);
        }
        #pragma unroll
        for (int o = 16; o > 0; o >>= 1) mx = fmaxf(mx, __shfl_xor_sync(0xffffffffu, mx, o));
        float es = 0.f;
        #pragma unroll
        for (int mm = 0; mm < 6; mm++) { vals[mm] = __expf(vals[mm] - mx); es += vals[mm]; }
        #pragma unroll
        for (int o = 16; o > 0; o >>= 1) es += __shfl_xor_sync(0xffffffffu, es, o);
        float inv = 1.f / es;
        #pragma unroll
        for (int mm = 0; mm < 6; mm++) sS[r*196 + lane + 32*mm] = vals[mm] * inv;
    }
    __syncthreads();
    // Pp = probs @ Wv  (m=64, n=48, k=192); 4m x 3n warps, tile 16x16
    int gid = lane >> 2, tig = lane & 3;
    int wr = w & 3, wc = w >> 2;
    int m0 = wr*16, n0 = wc*16;
    float cacc[2][4];
    #pragma unroll
    for (int j = 0; j < 2; j++)
        #pragma unroll
        for (int q = 0; q < 4; q++) cacc[j][q] = 0.f;
    for (int ks = 0; ks < KVd; ks += 8) {
        uint32_t a[4], bb[2][2];
        a[0] = bits(sS[(m0+gid)*196 + ks+tig]);
        a[1] = bits(sS[(m0+8+gid)*196 + ks+tig]);
        a[2] = bits(sS[(m0+gid)*196 + ks+tig+4]);
        a[3] = bits(sS[(m0+8+gid)*196 + ks+tig+4]);
        #pragma unroll
        for (int j = 0; j < 2; j++) {
            int c0 = n0 + j*8;
            bb[j][0] = bits(sV[(ks+tig)*52 + c0+gid]);
            bb[j][1] = bits(sV[(ks+tig+4)*52 + c0+gid]);
        }
        #pragma unroll
        for (int j = 0; j < 2; j++)
            mma_tf32(cacc[j], a, bb[j]);
    }
    float* out = g_Pp + (size_t)bh*GSZ;
    int r_lo = m0 + gid, r_hi = r_lo + 8;
    #pragma unroll
    for (int j = 0; j < 2; j++) {
        int c0 = tile*48 + n0 + j*8 + 2*tig;
        *(float2*)(out + r_lo*KVd + c0) = make_float2(cacc[j][0], cacc[j][1]);
        *(float2*)(out + r_hi*KVd + c0) = make_float2(cacc[j][2], cacc[j][3]);
    }
}

// ============ 4) M = Wout @ mean_h(Pp)  (tf32 mma, grid (8,4)) ============
__global__ __launch_bounds__(128,4) void mmat_kernel(const float* __restrict__ Wout) {
    float* sP = dsm;                 // [64][52]  Pbar tile (rows c=k, cols k2=n)
    float* sW = dsm + 64*52;         // [64][68]  Wout row-major
    int b = blockIdx.x, tile = blockIdx.y;
    int tid = threadIdx.x;
    for (int i = tid; i < 64*12; i += 128) {
        int c = i / 12, k = (i % 12)*4;
        size_t off = (size_t)(b*Hh)*GSZ + c*KVd + tile*48 + k;
        float4 p0 = *(const float4*)(g_Pp + off);
        float4 p1 = *(const float4*)(g_Pp + off + GSZ);
        float4 p2 = *(const float4*)(g_Pp + off + 2*GSZ);
        float4 p3 = *(const float4*)(g_Pp + off + 3*GSZ);
        float4 s4;
        s4.x = (p0.x + p1.x + p2.x + p3.x) * 0.25f;
        s4.y = (p0.y + p1.y + p2.y + p3.y) * 0.25f;
        s4.z = (p0.z + p1.z + p2.z + p3.z) * 0.25f;
        s4.w = (p0.w + p1.w + p2.w + p3.w) * 0.25f;
        *(float4*)(sP + c*52 + k) = s4;
    }
    for (int i = tid; i < 1024; i += 128) {
        int d = i >> 4, c = (i & 15)*4;
        *(float4*)(sW + d*68 + c) = *(const float4*)(Wout + d*C1d + c);
    }
    __syncthreads();
    int w = tid >> 5, lane = tid & 31;
    int gid = lane >> 2, tig = lane & 3;
    int m0 = w*16;
    float cacc[6][4];
    #pragma unroll
    for (int j = 0; j < 6; j++)
        #pragma unroll
        for (int q = 0; q < 4; q++) cacc[j][q] = 0.f;
    for (int ks = 0; ks < C1d; ks += 8) {
        uint32_t a[4], bb[6][2];
        a[0] = bits(sW[(m0+gid)*68 + ks+tig]);
        a[1] = bits(sW[(m0+8+gid)*68 + ks+tig]);
        a[2] = bits(sW[(m0+gid)*68 + ks+tig+4]);
        a[3] = bits(sW[(m0+8+gid)*68 + ks+tig+4]);
        #pragma unroll
        for (int j = 0; j < 6; j++) {
            int c0 = j*8;
            bb[j][0] = bits(sP[(ks+tig)*52 + c0+gid]);
            bb[j][1] = bits(sP[(ks+tig+4)*52 + c0+gid]);
        }
        #pragma unroll
        for (int j = 0; j < 6; j++)
            mma_tf32(cacc[j], a, bb[j]);
    }
    float* out = g_M + (size_t)b*GSZ;
    int r_lo = m0 + gid, r_hi = r_lo + 8;
    #pragma unroll
    for (int j = 0; j < 6; j++) {
        int c0 = tile*48 + j*8 + 2*tig;
        *(float2*)(out + r_lo*KVd + c0) = make_float2(cacc[j][0], cacc[j][1]);
        *(float2*)(out + r_hi*KVd + c0) = make_float2(cacc[j][2], cacc[j][3]);
    }
}

// ============ 5) fused tail (tf32 mma, raw fp32 operands) ======
__device__ __forceinline__ float gelu_exact(float x) {
    return 0.5f * x * (1.f + erff(x * 0.70710678118654752f));
}

#define T_HS   0                      /* Hs [64][260]=16640 ; alias sEA [64][196]=12544 */
#define T_XN   16640                  /* Xn [64][68] =4352  */
#define T_TOT  20992                  /* *4 = 83968 B */

__global__ __launch_bounds__(256,2) void tail_kernel(
        const float* __restrict__ emb1,
        const float* __restrict__ fc1w, const float* __restrict__ fc2w,
        const float* __restrict__ fc1b, const float* __restrict__ fc2b,
        const float* __restrict__ fg, const float* __restrict__ fb,
        float* __restrict__ out) {
    float* sEA = dsm + T_HS;           // [64][196]
    float* Hs  = dsm + T_HS;           // [64][260]  (after octx)
    float* Xn  = dsm + T_XN;           // [64][68]
    __shared__ float ms[64], rss[64];
    int ch = blockIdx.x, b = blockIdx.y;
    int base = b*Nn + ch*64;
    int tid = threadIdx.x;
    int w = tid >> 5, lane = tid & 31;
    int gid = lane >> 2, tig = lane & 3;
    int wr = w >> 2, wc = w & 3;       // warp grid 2 x 4
    const float* Mb = g_M + (size_t)b*GSZ;

    for (int i = tid; i < 64*48; i += 256) {
        int r = i / 48, k = (i % 48)*4;
        *(float4*)(sEA + r*196 + k) = *(const float4*)(g_ea + (size_t)base*KVd + r*KVd + k);
    }
    __syncthreads();

    // ---- octx: C[64,64] = EA @ M^T; warp tile 32 rows x 16 cols ----
    float cx[2][2][4];
    {
        float cacc[2][2][4];
        #pragma unroll
        for (int i = 0; i < 2; i++)
            #pragma unroll
            for (int j = 0; j < 2; j++)
                #pragma unroll
                for (int q = 0; q < 4; q++) cacc[i][j][q] = 0.f;
        for (int ks = 0; ks < KVd; ks += 8) {
            uint32_t a[2][4], bb[2][2];
            #pragma unroll
            for (int i = 0; i < 2; i++) {
                int r0 = wr*32 + i*16;
                a[i][0] = bits(sEA[(r0+gid)*196 + ks+tig]);
                a[i][1] = bits(sEA[(r0+8+gid)*196 + ks+tig]);
                a[i][2] = bits(sEA[(r0+gid)*196 + ks+tig+4]);
                a[i][3] = bits(sEA[(r0+8+gid)*196 + ks+tig+4]);
            }
            #pragma unroll
            for (int j = 0; j < 2; j++) {
                int c0 = wc*16 + j*8;
                bb[j][0] = bits(__ldg(Mb + (c0+gid)*KVd + ks+tig));
                bb[j][1] = bits(__ldg(Mb + (c0+gid)*KVd + ks+tig+4));
            }
            #pragma unroll
            for (int i = 0; i < 2; i++)
                #pragma unroll
                for (int j = 0; j < 2; j++)
                    mma_tf32(cacc[i][j], a[i], bb[j]);
        }
        #pragma unroll
        for (int i = 0; i < 2; i++) {
            int r_lo = wr*32 + i*16 + gid, r_hi = r_lo + 8;
            #pragma unroll
            for (int j = 0; j < 2; j++) {
                int c0 = wc*16 + j*8 + 2*tig;
                float2 e0 = *(const float2*)(emb1 + (size_t)(base+r_lo)*C1d + c0);
                float2 e1 = *(const float2*)(emb1 + (size_t)(base+r_hi)*C1d + c0);
                cx[i][j][0] = cacc[i][j][0] + e0.x;
                cx[i][j][1] = cacc[i][j][1] + e0.y;
                cx[i][j][2] = cacc[i][j][2] + e1.x;
                cx[i][j][3] = cacc[i][j][3] + e1.y;
                *(float2*)(Xn + r_lo*68 + c0) = make_float2(cx[i][j][0], cx[i][j][1]);
                *(float2*)(Xn + r_hi*68 + c0) = make_float2(cx[i][j][2], cx[i][j][3]);
            }
        }
    }
    __syncthreads();
    if (tid < 64) {
        float s = 0.f, q = 0.f;
        const float* row = Xn + tid*68;
        #pragma unroll 8
        for (int c = 0; c < C1d; c++) { float v = row[c]; s += v; q += v*v; }
        float m = s * (1.f/C1d);
        float v = q * (1.f/C1d) - m*m;
        ms[tid] = m; rss[tid] = rsqrtf(v + 1e-6f);
    }
    __syncthreads();
    for (int i = tid; i < 64*C1d; i += 256) {
        int r = i >> 6, c = i & 63;
        Xn[r*68 + c] = (Xn[r*68 + c] - ms[r]) * rss[r] * __ldg(fg + c) + __ldg(fb + c);
    }
    __syncthreads();

    // ---- fc1 + gelu: H[64,256] = Xn @ W1^T; warp tile 32 rows x 64 cols ----
    {
        float h[2][8][4];
        #pragma unroll
        for (int i = 0; i < 2; i++)
            #pragma unroll
            for (int j = 0; j < 8; j++)
                #pragma unroll
                for (int q = 0; q < 4; q++) h[i][j][q] = 0.f;
        for (int ks = 0; ks < C1d; ks += 8) {
            uint32_t a[2][4], bb[8][2];
            #pragma unroll
            for (int i = 0; i < 2; i++) {
                int r0 = wr*32 + i*16;
                a[i][0] = bits(Xn[(r0+gid)*68 + ks+tig]);
                a[i][1] = bits(Xn[(r0+8+gid)*68 + ks+tig]);
                a[i][2] = bits(Xn[(r0+gid)*68 + ks+tig+4]);
                a[i][3] = bits(Xn[(r0+8+gid)*68 + ks+tig+4]);
            }
            #pragma unroll
            for (int j = 0; j < 8; j++) {
                int c0 = wc*64 + j*8;
                bb[j][0] = bits(__ldg(fc1w + (c0+gid)*C1d + ks+tig));
                bb[j][1] = bits(__ldg(fc1w + (c0+gid)*C1d + ks+tig+4));
            }
            #pragma unroll
            for (int i = 0; i < 2; i++)
                #pragma unroll
                for (int j = 0; j < 8; j++)
                    mma_tf32(h[i][j], a[i], bb[j]);
        }
        __syncthreads();
        #pragma unroll
        for (int i = 0; i < 2; i++) {
            int r_lo = wr*32 + i*16 + gid, r_hi = r_lo + 8;
            #pragma unroll
            for (int j = 0; j < 8; j++) {
                int c0 = wc*64 + j*8 + 2*tig;
                float2 bj = *(const float2*)(fc1b + c0);
                *(float2*)(Hs + r_lo*260 + c0) =
                    make_float2(gelu_exact(h[i][j][0] + bj.x), gelu_exact(h[i][j][1] + bj.y));
                *(float2*)(Hs + r_hi*260 + c0) =
                    make_float2(gelu_exact(h[i][j][2] + bj.x), gelu_exact(h[i][j][3] + bj.y));
            }
        }
    }
    __syncthreads();

    // ---- fc2 + bias + residual ----
    {
        float oacc[2][2][4];
        #pragma unroll
        for (int i = 0; i < 2; i++)
            #pragma unroll
            for (int j = 0; j < 2; j++)
                #pragma unroll
                for (int q = 0; q < 4; q++) oacc[i][j][q] = 0.f;
        for (int ks = 0; ks < MLPd; ks += 8) {
            uint32_t a[2][4], bb[2][2];
            #pragma unroll
            for (int i = 0; i < 2; i++) {
                int r0 = wr*32 + i*16;
                a[i][0] = bits(Hs[(r0+gid)*260 + ks+tig]);
                a[i][1] = bits(Hs[(r0+8+gid)*260 + ks+tig]);
                a[i][2] = bits(Hs[(r0+gid)*260 + ks+tig+4]);
                a[i][3] = bits(Hs[(r0+8+gid)*260 + ks+tig+4]);
            }
            #pragma unroll
            for (int j = 0; j < 2; j++) {
                int c0 = wc*16 + j*8;
                bb[j][0] = bits(__ldg(fc2w + (c0+gid)*MLPd + ks+tig));
                bb[j][1] = bits(__ldg(fc2w + (c0+gid)*MLPd + ks+tig+4));
            }
            #pragma unroll
            for (int i = 0; i < 2; i++)
                #pragma unroll
                for (int j = 0; j < 2; j++)
                    mma_tf32(oacc[i][j], a[i], bb[j]);
        }
        #pragma unroll
        for (int i = 0; i < 2; i++) {
            int r_lo = wr*32 + i*16 + gid, r_hi = r_lo + 8;
            #pragma unroll
            for (int j = 0; j < 2; j++) {
                int c0 = wc*16 + j*8 + 2*tig;
                float2 b2 = *(const float2*)(fc2b + c0);
                float2 o0, o1;
                o0.x = oacc[i][j][0] + b2.x + cx[i][j][0];
                o0.y = oacc[i][j][1] + b2.y + cx[i][j][1];
                o1.x = oacc[i][j][2] + b2.x + cx[i][j][2];
                o1.y = oacc[i][j][3] + b2.y + cx[i][j][3];
                *(float2*)(out + (size_t)(base+r_lo)*C1d + c0) = o0;
                *(float2*)(out + (size_t)(base+r_hi)*C1d + c0) = o1;
            }
        }
    }
}

// ---------------- launch ----------------
extern "C" void kernel_launch(void* const* d_in, const int* in_sizes, int n_in,
                              void* d_out, int out_size) {
    const float* emb1   = (const float*)d_in[0];
    const float* emb2   = (const float*)d_in[1];
    const float* Wq     = (const float*)d_in[2];
    const float* Wk     = (const float*)d_in[3];
    const float* Wv     = (const float*)d_in[4];
    const float* Wout   = (const float*)d_in[5];
    const float* ln1_g  = (const float*)d_in[6];
    const float* ln1_b  = (const float*)d_in[7];
    const float* lnA_g  = (const float*)d_in[8];
    const float* lnA_b  = (const float*)d_in[9];
    const float* ffn_g  = (const float*)d_in[10];
    const float* ffn_b  = (const float*)d_in[11];
    const float* fc1_w  = (const float*)d_in[12];
    const float* fc1_b  = (const float*)d_in[13];
    const float* fc2_w  = (const float*)d_in[14];
    const float* fc2_b  = (const float*)d_in[15];
    float* out = (float*)d_out;

    const int smem_gmatln = (64*196 + 64*65) * 4;                    // 66816
    const int smem_smatT  = (64*196 + 64*196 + 64*68 + 192*52) * 4;  // 157696
    const int smem_pmat   = (64*196 + 192*52) * 4;                   // 90112
    const int smem_mmat   = (64*52 + 64*68) * 4;                     // 30720
    const int smem_tail   = T_TOT * 4;                               // 83968

    cudaFuncSetAttribute(gmatln_kernel, cudaFuncAttributeMaxDynamicSharedMemorySize, smem_gmatln);
    cudaFuncSetAttribute(smatT_kernel,  cudaFuncAttributeMaxDynamicSharedMemorySize, smem_smatT);
    cudaFuncSetAttribute(pmat_kernel,   cudaFuncAttributeMaxDynamicSharedMemorySize, smem_pmat);
    cudaFuncSetAttribute(mmat_kernel,   cudaFuncAttributeMaxDynamicSharedMemorySize, smem_mmat);
    cudaFuncSetAttribute(tail_kernel,   cudaFuncAttributeMaxDynamicSharedMemorySize, smem_tail);

    init_kernel<<<(Bq*GSZ)/256, 256>>>();
    gmatln_kernel<<<dim3(NCH, Bq), 256, smem_gmatln>>>(emb1, emb2, ln1_g, ln1_b, lnA_g, lnA_b);
    smatT_kernel<<<dim3(Bq*Hh, 4), 384, smem_smatT>>>(Wq, Wk);
    pmat_kernel<<<dim3(Bq*Hh, 4), 384, smem_pmat>>>(Wv);
    mmat_kernel<<<dim3(Bq, 4), 128, smem_mmat>>>(Wout);
    tail_kernel<<<dim3(NCH, Bq), 256, smem_tail>>>(emb1, fc1_w, fc2_w, fc1_b, fc2_b, ffn_g, ffn_b, out);
}

// round 12
// speedup vs baseline: 1.4657x; 1.4657x over previous
#include <cuda_runtime.h>
#include <math.h>
#include <stdint.h>

#define Bq   8
#define Nn   3136
#define C1d  64
#define C2d  128
#define KVd  192
#define Hh   4
#define MLPd 256
#define NROW (Bq*Nn)     /* 25088 */
#define NCH  49          /* 3136 / 64 */
#define GSZ  (C1d*KVd)   /* 12288 */

// ---------------- scratch (device globals; no allocation) ----------------
__device__ float g_ea[NROW*KVd];          // LN(concat) rows (fp32; mma truncates)
__device__ float g_G[Bq*GSZ];             // fp32 atomic-accumulated G
__device__ float g_S[Bq*Hh*GSZ];          // scores (scaled, pre-IN, fp32)
__device__ float2 g_pstats[Bq*Hh*4];      // per-tile (sum, sumsq) of scores
__device__ float g_Pp[Bq*Hh*GSZ];         // probs @ Wv (fp32)
__device__ float g_M[Bq*GSZ];             // M

extern __shared__ float dsm[];

__device__ __forceinline__ uint32_t bits(float f) { return __float_as_uint(f); }
// mma reads the top 19 bits of each operand -> fp32 bits act as RZ-truncated tf32
__device__ __forceinline__ void mma_tf32(float* c, const uint32_t* a, const uint32_t* b) {
    asm volatile("mma.sync.aligned.m16n8k8.row.col.f32.tf32.tf32.f32 "
        "{%0,%1,%2,%3}, {%4,%5,%6,%7}, {%8,%9}, {%0,%1,%2,%3};"
        : "+f"(c[0]), "+f"(c[1]), "+f"(c[2]), "+f"(c[3])
        : "r"(a[0]), "r"(a[1]), "r"(a[2]), "r"(a[3]), "r"(b[0]), "r"(b[1]));
}

// ============ 0) init: zero g_G ============
__global__ void init_kernel() {
    g_G[blockIdx.x*256 + threadIdx.x] = 0.f;
}

// ============ 1) fused dual-LayerNorm + G partial -> atomicAdd into g_G =====
// grid (49, 8), 256 threads
__global__ __launch_bounds__(256,2) void gmatln_kernel(
        const float* __restrict__ emb1, const float* __restrict__ emb2,
        const float* __restrict__ g1, const float* __restrict__ b1,
        const float* __restrict__ gA, const float* __restrict__ bA) {
    float* sE = dsm;                 // [64][196] raw -> ea
    float* sC = dsm + 64*196;        // [64][65]  cx1
    __shared__ float m1s[64], r1s[64], mAs[64], rAs[64];
    int ch = blockIdx.x, b = blockIdx.y;
    int base = b*Nn + ch*64;
    int tid = threadIdx.x;
    for (int i = tid; i < 64*48; i += 256) {
        int r = i / 48, c = (i % 48)*4;
        float4 v = (c < C1d) ? *(const float4*)(emb1 + (size_t)(base+r)*C1d + c)
                             : *(const float4*)(emb2 + (size_t)(base+r)*C2d + (c - C1d));
        *(float4*)(sE + r*196 + c) = v;
    }
    __syncthreads();
    if (tid < 64) {
        float s1 = 0.f, q1 = 0.f, s2 = 0.f, q2 = 0.f;
        const float* row = sE + tid*196;
        #pragma unroll 8
        for (int c = 0; c < C1d; c++)  { float v = row[c]; s1 += v; q1 += v*v; }
        #pragma unroll 8
        for (int c = C1d; c < KVd; c++){ float v = row[c]; s2 += v; q2 += v*v; }
        float m1 = s1 * (1.f/C1d);
        float v1 = q1 * (1.f/C1d) - m1*m1;
        m1s[tid] = m1; r1s[tid] = rsqrtf(v1 + 1e-6f);
        float mA = (s1+s2) * (1.f/KVd);
        float vA = (q1+q2) * (1.f/KVd) - mA*mA;
        mAs[tid] = mA; rAs[tid] = rsqrtf(vA + 1e-6f);
    }
    __syncthreads();
    for (int i = tid; i < 64*48; i += 256) {
        int r = i / 48, c = (i % 48)*4;
        float4 v = *(const float4*)(sE + r*196 + c);
        float4 g = *(const float4*)(gA + c);
        float4 bb4 = *(const float4*)(bA + c);
        float mA = mAs[r], rA = rAs[r];
        float4 ea;
        ea.x = (v.x - mA)*rA*g.x + bb4.x;
        ea.y = (v.y - mA)*rA*g.y + bb4.y;
        ea.z = (v.z - mA)*rA*g.z + bb4.z;
        ea.w = (v.w - mA)*rA*g.w + bb4.w;
        *(float4*)(sE + r*196 + c) = ea;
        *(float4*)(g_ea + (size_t)(base+r)*KVd + c) = ea;
        if (c < C1d) {
            float m1 = m1s[r], r1 = r1s[r];
            sC[r*65 + c+0] = (v.x - m1)*r1*__ldg(g1 + c+0) + __ldg(b1 + c+0);
            sC[r*65 + c+1] = (v.y - m1)*r1*__ldg(g1 + c+1) + __ldg(b1 + c+1);
            sC[r*65 + c+2] = (v.z - m1)*r1*__ldg(g1 + c+2) + __ldg(b1 + c+2);
            sC[r*65 + c+3] = (v.w - m1)*r1*__ldg(g1 + c+3) + __ldg(b1 + c+3);
        }
    }
    __syncthreads();
    int w = tid >> 5, lane = tid & 31;
    int gid = lane >> 2, tig = lane & 3;
    int wr = w >> 2, wc = w & 3;       // 2 x 4 warps; tile 32m x 48n
    float cacc[2][6][4];
    #pragma unroll
    for (int i = 0; i < 2; i++)
        #pragma unroll
        for (int j = 0; j < 6; j++)
            #pragma unroll
            for (int q = 0; q < 4; q++) cacc[i][j][q] = 0.f;
    for (int ks = 0; ks < C1d; ks += 8) {
        uint32_t a[2][4], bb[6][2];
        #pragma unroll
        for (int i = 0; i < 2; i++) {
            int m0 = wr*32 + i*16;
            a[i][0] = bits(sC[(ks+tig)*65 + m0+gid]);
            a[i][1] = bits(sC[(ks+tig)*65 + m0+8+gid]);
            a[i][2] = bits(sC[(ks+tig+4)*65 + m0+gid]);
            a[i][3] = bits(sC[(ks+tig+4)*65 + m0+8+gid]);
        }
        #pragma unroll
        for (int j = 0; j < 6; j++) {
            int n0 = wc*48 + j*8;
            bb[j][0] = bits(sE[(ks+tig)*196 + n0+gid]);
            bb[j][1] = bits(sE[(ks+tig+4)*196 + n0+gid]);
        }
        #pragma unroll
        for (int i = 0; i < 2; i++)
            #pragma unroll
            for (int j = 0; j < 6; j++)
                mma_tf32(cacc[i][j], a[i], bb[j]);
    }
    float* out = g_G + (size_t)b*GSZ;
    #pragma unroll
    for (int i = 0; i < 2; i++) {
        int r_lo = wr*32 + i*16 + gid, r_hi = r_lo + 8;
        #pragma unroll
        for (int j = 0; j < 6; j++) {
            int c0 = wc*48 + j*8 + 2*tig;
            atomicAdd(out + r_lo*KVd + c0,     cacc[i][j][0]);
            atomicAdd(out + r_lo*KVd + c0 + 1, cacc[i][j][1]);
            atomicAdd(out + r_hi*KVd + c0,     cacc[i][j][2]);
            atomicAdd(out + r_hi*KVd + c0 + 1, cacc[i][j][3]);
        }
    }
}

// ============ 2) fused T=Wq@G, S = T@Wk^T/sqrt(KV) + partial stats =====
// grid (32, 4), 256 threads
__global__ __launch_bounds__(256,1) void smatT_kernel(
        const float* __restrict__ Wq, const float* __restrict__ Wk) {
    float* sG  = dsm;                  // [64][196]
    float* sT  = dsm + 64*196;         // [64][196]
    float* sWq = sT + 64*196;          // [64][68]   Wq row-major
    float* sWk = sWq + 64*68;          // [192][52]  Wk^T tile
    __shared__ float redS[8], redQ[8];
    int bh = blockIdx.x, tile = blockIdx.y;
    int b = bh >> 2, h = bh & 3;
    int tid = threadIdx.x;
    for (int i = tid; i < 64*48; i += 256) {
        int c = i / 48, k = (i % 48)*4;
        *(float4*)(sG + c*196 + k) = *(const float4*)(g_G + (size_t)b*GSZ + c*KVd + k);
    }
    for (int i = tid; i < 1024; i += 256) {
        int d = i >> 4, c = (i & 15)*4;
        *(float4*)(sWq + d*68 + c) = *(const float4*)(Wq + (size_t)h*C1d*C1d + d*C1d + c);
    }
    for (int i = tid; i < 48*48; i += 256) {
        int j = i / 48, kp = (i % 48)*4;
        float4 v = *(const float4*)(Wk + (size_t)h*KVd*KVd + (tile*48 + j)*KVd + kp);
        sWk[(kp+0)*52 + j] = v.x;
        sWk[(kp+1)*52 + j] = v.y;
        sWk[(kp+2)*52 + j] = v.z;
        sWk[(kp+3)*52 + j] = v.w;
    }
    __syncthreads();
    int w = tid >> 5, lane = tid & 31;
    int gid = lane >> 2, tig = lane & 3;
    // Phase 1: T = Wq @ G  (m=64, n=192, k=64); warps 2x4, tile 32x48
    {
        int wr = w >> 2, wc = w & 3;
        float cacc[2][6][4];
        #pragma unroll
        for (int i = 0; i < 2; i++)
            #pragma unroll
            for (int j = 0; j < 6; j++)
                #pragma unroll
                for (int q = 0; q < 4; q++) cacc[i][j][q] = 0.f;
        for (int ks = 0; ks < C1d; ks += 8) {
            uint32_t a[2][4], bb[6][2];
            #pragma unroll
            for (int i = 0; i < 2; i++) {
                int m0 = wr*32 + i*16;
                a[i][0] = bits(sWq[(m0+gid)*68 + ks+tig]);
                a[i][1] = bits(sWq[(m0+8+gid)*68 + ks+tig]);
                a[i][2] = bits(sWq[(m0+gid)*68 + ks+tig+4]);
                a[i][3] = bits(sWq[(m0+8+gid)*68 + ks+tig+4]);
            }
            #pragma unroll
            for (int j = 0; j < 6; j++) {
                int n0 = wc*48 + j*8;
                bb[j][0] = bits(sG[(ks+tig)*196 + n0+gid]);
                bb[j][1] = bits(sG[(ks+tig+4)*196 + n0+gid]);
            }
            #pragma unroll
            for (int i = 0; i < 2; i++)
                #pragma unroll
                for (int j = 0; j < 6; j++)
                    mma_tf32(cacc[i][j], a[i], bb[j]);
        }
        #pragma unroll
        for (int i = 0; i < 2; i++) {
            int r_lo = wr*32 + i*16 + gid, r_hi = r_lo + 8;
            #pragma unroll
            for (int j = 0; j < 6; j++) {
                int c0 = wc*48 + j*8 + 2*tig;
                *(float2*)(sT + r_lo*196 + c0) = make_float2(cacc[i][j][0], cacc[i][j][1]);
                *(float2*)(sT + r_hi*196 + c0) = make_float2(cacc[i][j][2], cacc[i][j][3]);
            }
        }
    }
    __syncthreads();
    // Phase 2: S = T @ Wk^T * scale  (m=64, n=48, k=192); warps 4x2, tile 16x24
    // register double-buffered k-loop
    const float scale = 0.0721687836487f;   // 1/sqrt(192)
    float lsum = 0.f, lsq = 0.f;
    {
        int wr = w >> 1, wc = w & 1;
        int m0 = wr*16, n0 = wc*24;
        float cacc[3][4];
        #pragma unroll
        for (int j = 0; j < 3; j++)
            #pragma unroll
            for (int q = 0; q < 4; q++) cacc[j][q] = 0.f;
        uint32_t a[2][4], bb[2][3][2];
        // preload ks=0
        a[0][0] = bits(sT[(m0+gid)*196 + tig]);
        a[0][1] = bits(sT[(m0+8+gid)*196 + tig]);
        a[0][2] = bits(sT[(m0+gid)*196 + tig+4]);
        a[0][3] = bits(sT[(m0+8+gid)*196 + tig+4]);
        #pragma unroll
        for (int j = 0; j < 3; j++) {
            int c0 = n0 + j*8;
            bb[0][j][0] = bits(sWk[(tig)*52 + c0+gid]);
            bb[0][j][1] = bits(sWk[(tig+4)*52 + c0+gid]);
        }
        #pragma unroll
        for (int it = 0; it < 24; it++) {
            int cur = it & 1, nxt = cur ^ 1;
            int ksn = (it+1)*8;
            if (it < 23) {
                a[nxt][0] = bits(sT[(m0+gid)*196 + ksn+tig]);
                a[nxt][1] = bits(sT[(m0+8+gid)*196 + ksn+tig]);
                a[nxt][2] = bits(sT[(m0+gid)*196 + ksn+tig+4]);
                a[nxt][3] = bits(sT[(m0+8+gid)*196 + ksn+tig+4]);
                #pragma unroll
                for (int j = 0; j < 3; j++) {
                    int c0 = n0 + j*8;
                    bb[nxt][j][0] = bits(sWk[(ksn+tig)*52 + c0+gid]);
                    bb[nxt][j][1] = bits(sWk[(ksn+tig+4)*52 + c0+gid]);
                }
            }
            #pragma unroll
            for (int j = 0; j < 3; j++)
                mma_tf32(cacc[j], a[cur], bb[cur][j]);
        }
        float* out = g_S + (size_t)bh*GSZ;
        int r_lo = m0 + gid, r_hi = r_lo + 8;
        #pragma unroll
        for (int j = 0; j < 3; j++) {
            int c0 = tile*48 + n0 + j*8 + 2*tig;
            float v0 = cacc[j][0]*scale, v1 = cacc[j][1]*scale;
            float v2 = cacc[j][2]*scale, v3 = cacc[j][3]*scale;
            *(float2*)(out + r_lo*KVd + c0) = make_float2(v0, v1);
            *(float2*)(out + r_hi*KVd + c0) = make_float2(v2, v3);
            lsum += v0+v1+v2+v3;
            lsq  += v0*v0+v1*v1+v2*v2+v3*v3;
        }
    }
    #pragma unroll
    for (int o = 16; o > 0; o >>= 1) {
        lsum += __shfl_down_sync(0xffffffffu, lsum, o);
        lsq  += __shfl_down_sync(0xffffffffu, lsq, o);
    }
    if (lane == 0) { redS[w] = lsum; redQ[w] = lsq; }
    __syncthreads();
    if (tid == 0) {
        float s = 0.f, q = 0.f;
        #pragma unroll
        for (int i = 0; i < 8; i++) { s += redS[i]; q += redQ[i]; }
        g_pstats[bh*4 + tile] = make_float2(s, q);
    }
}

// ============ 3) fused IN + softmax + Pp = probs @ Wv ========
// grid (32, 4), 256 threads
__global__ __launch_bounds__(256,2) void pmat_kernel(const float* __restrict__ Wv) {
    float* sS = dsm;                   // [64][196] scores -> probs
    float* sV = dsm + 64*196;          // [192][52] Wv tile
    __shared__ float s_m, s_rs;
    int bh = blockIdx.x, h = bh & 3, tile = blockIdx.y;
    int tid = threadIdx.x;
    for (int i = tid; i < 64*48; i += 256) {
        int c = i / 48, k = (i % 48)*4;
        *(float4*)(sS + c*196 + k) = *(const float4*)(g_S + (size_t)bh*GSZ + c*KVd + k);
    }
    for (int i = tid; i < 192*12; i += 256) {
        int k = i / 12, c = (i % 12)*4;
        *(float4*)(sV + k*52 + c) = *(const float4*)(Wv + (size_t)h*KVd*KVd + k*KVd + tile*48 + c);
    }
    if (tid == 0) {
        float s = 0.f, q = 0.f;
        #pragma unroll
        for (int t = 0; t < 4; t++) {
            float2 p = g_pstats[bh*4 + t];
            s += p.x; q += p.y;
        }
        float m = s * (1.f/GSZ);
        float v = q * (1.f/GSZ) - m*m;
        s_m = m; s_rs = rsqrtf(v + 1e-5f);
    }
    __syncthreads();
    float mean = s_m, rs = s_rs;
    int w = tid >> 5, lane = tid & 31;
    for (int r = w; r < C1d; r += 8) {
        float vals[6];
        float mx = -1e30f;
        #pragma unroll
        for (int mm = 0; mm < 6; mm++) {
            vals[mm] = (sS[r*196 + lane + 32*mm] - mean) * rs;
            mx = fmaxf(mx, vals[mm]);
        }
        #pragma unroll
        for (int o = 16; o > 0; o >>= 1) mx = fmaxf(mx, __shfl_xor_sync(0xffffffffu, mx, o));
        float es = 0.f;
        #pragma unroll
        for (int mm = 0; mm < 6; mm++) { vals[mm] = __expf(vals[mm] - mx); es += vals[mm]; }
        #pragma unroll
        for (int o = 16; o > 0; o >>= 1) es += __shfl_xor_sync(0xffffffffu, es, o);
        float inv = 1.f / es;
        #pragma unroll
        for (int mm = 0; mm < 6; mm++) sS[r*196 + lane + 32*mm] = vals[mm] * inv;
    }
    __syncthreads();
    // Pp = probs @ Wv  (m=64, n=48, k=192); warps 4x2, tile 16x24
    // register double-buffered k-loop
    int gid = lane >> 2, tig = lane & 3;
    int wr = w >> 1, wc = w & 1;
    int m0 = wr*16, n0 = wc*24;
    float cacc[3][4];
    #pragma unroll
    for (int j = 0; j < 3; j++)
        #pragma unroll
        for (int q = 0; q < 4; q++) cacc[j][q] = 0.f;
    uint32_t a[2][4], bb[2][3][2];
    a[0][0] = bits(sS[(m0+gid)*196 + tig]);
    a[0][1] = bits(sS[(m0+8+gid)*196 + tig]);
    a[0][2] = bits(sS[(m0+gid)*196 + tig+4]);
    a[0][3] = bits(sS[(m0+8+gid)*196 + tig+4]);
    #pragma unroll
    for (int j = 0; j < 3; j++) {
        int c0 = n0 + j*8;
        bb[0][j][0] = bits(sV[(tig)*52 + c0+gid]);
        bb[0][j][1] = bits(sV[(tig+4)*52 + c0+gid]);
    }
    #pragma unroll
    for (int it = 0; it < 24; it++) {
        int cur = it & 1, nxt = cur ^ 1;
        int ksn = (it+1)*8;
        if (it < 23) {
            a[nxt][0] = bits(sS[(m0+gid)*196 + ksn+tig]);
            a[nxt][1] = bits(sS[(m0+8+gid)*196 + ksn+tig]);
            a[nxt][2] = bits(sS[(m0+gid)*196 + ksn+tig+4]);
            a[nxt][3] = bits(sS[(m0+8+gid)*196 + ksn+tig+4]);
            #pragma unroll
            for (int j = 0; j < 3; j++) {
                int c0 = n0 + j*8;
                bb[nxt][j][0] = bits(sV[(ksn+tig)*52 + c0+gid]);
                bb[nxt][j][1] = bits(sV[(ksn+tig+4)*52 + c0+gid]);
            }
        }
        #pragma unroll
        for (int j = 0; j < 3; j++)
            mma_tf32(cacc[j], a[cur], bb[cur][j]);
    }
    float* out = g_Pp + (size_t)bh*GSZ;
    int r_lo = m0 + gid, r_hi = r_lo + 8;
    #pragma unroll
    for (int j = 0; j < 3; j++) {
        int c0 = tile*48 + n0 + j*8 + 2*tig;
        *(float2*)(out + r_lo*KVd + c0) = make_float2(cacc[j][0], cacc[j][1]);
        *(float2*)(out + r_hi*KVd + c0) = make_float2(cacc[j][2], cacc[j][3]);
    }
}

// ============ 4) M = Wout @ mean_h(Pp)  (tf32 mma, grid (8,4)) ============
__global__ __launch_bounds__(128,4) void mmat_kernel(const float* __restrict__ Wout) {
    float* sP = dsm;                 // [64][52]  Pbar tile (rows c=k, cols k2=n)
    float* sW = dsm + 64*52;         // [64][68]  Wout row-major
    int b = blockIdx.x, tile = blockIdx.y;
    int tid = threadIdx.x;
    for (int i = tid; i < 64*12; i += 128) {
        int c = i / 12, k = (i % 12)*4;
        size_t off = (size_t)(b*Hh)*GSZ + c*KVd + tile*48 + k;
        float4 p0 = *(const float4*)(g_Pp + off);
        float4 p1 = *(const float4*)(g_Pp + off + GSZ);
        float4 p2 = *(const float4*)(g_Pp + off + 2*GSZ);
        float4 p3 = *(const float4*)(g_Pp + off + 3*GSZ);
        float4 s4;
        s4.x = (p0.x + p1.x + p2.x + p3.x) * 0.25f;
        s4.y = (p0.y + p1.y + p2.y + p3.y) * 0.25f;
        s4.z = (p0.z + p1.z + p2.z + p3.z) * 0.25f;
        s4.w = (p0.w + p1.w + p2.w + p3.w) * 0.25f;
        *(float4*)(sP + c*52 + k) = s4;
    }
    for (int i = tid; i < 1024; i += 128) {
        int d = i >> 4, c = (i & 15)*4;
        *(float4*)(sW + d*68 + c) = *(const float4*)(Wout + d*C1d + c);
    }
    __syncthreads();
    int w = tid >> 5, lane = tid & 31;
    int gid = lane >> 2, tig = lane & 3;
    int m0 = w*16;
    float cacc[6][4];
    #pragma unroll
    for (int j = 0; j < 6; j++)
        #pragma unroll
        for (int q = 0; q < 4; q++) cacc[j][q] = 0.f;
    for (int ks = 0; ks < C1d; ks += 8) {
        uint32_t a[4], bb[6][2];
        a[0] = bits(sW[(m0+gid)*68 + ks+tig]);
        a[1] = bits(sW[(m0+8+gid)*68 + ks+tig]);
        a[2] = bits(sW[(m0+gid)*68 + ks+tig+4]);
        a[3] = bits(sW[(m0+8+gid)*68 + ks+tig+4]);
        #pragma unroll
        for (int j = 0; j < 6; j++) {
            int c0 = j*8;
            bb[j][0] = bits(sP[(ks+tig)*52 + c0+gid]);
            bb[j][1] = bits(sP[(ks+tig+4)*52 + c0+gid]);
        }
        #pragma unroll
        for (int j = 0; j < 6; j++)
            mma_tf32(cacc[j], a, bb[j]);
    }
    float* out = g_M + (size_t)b*GSZ;
    int r_lo = m0 + gid, r_hi = r_lo + 8;
    #pragma unroll
    for (int j = 0; j < 6; j++) {
        int c0 = tile*48 + j*8 + 2*tig;
        *(float2*)(out + r_lo*KVd + c0) = make_float2(cacc[j][0], cacc[j][1]);
        *(float2*)(out + r_hi*KVd + c0) = make_float2(cacc[j][2], cacc[j][3]);
    }
}

// ============ 5) fused tail (tf32 mma, raw fp32 operands) ======
__device__ __forceinline__ float gelu_exact(float x) {
    return 0.5f * x * (1.f + erff(x * 0.70710678118654752f));
}

#define T_HS   0                      /* Hs [64][260]=16640 ; alias sEA [64][196]=12544 */
#define T_XN   16640                  /* Xn [64][68] =4352  */
#define T_TOT  20992                  /* *4 = 83968 B */

__global__ __launch_bounds__(256,2) void tail_kernel(
        const float* __restrict__ emb1,
        const float* __restrict__ fc1w, const float* __restrict__ fc2w,
        const float* __restrict__ fc1b, const float* __restrict__ fc2b,
        const float* __restrict__ fg, const float* __restrict__ fb,
        float* __restrict__ out) {
    float* sEA = dsm + T_HS;           // [64][196]
    float* Hs  = dsm + T_HS;           // [64][260]  (after octx)
    float* Xn  = dsm + T_XN;           // [64][68]
    __shared__ float ms[64], rss[64];
    int ch = blockIdx.x, b = blockIdx.y;
    int base = b*Nn + ch*64;
    int tid = threadIdx.x;
    int w = tid >> 5, lane = tid & 31;
    int gid = lane >> 2, tig = lane & 3;
    int wr = w >> 2, wc = w & 3;       // warp grid 2 x 4
    const float* Mb = g_M + (size_t)b*GSZ;

    for (int i = tid; i < 64*48; i += 256) {
        int r = i / 48, k = (i % 48)*4;
        *(float4*)(sEA + r*196 + k) = *(const float4*)(g_ea + (size_t)base*KVd + r*KVd + k);
    }
    __syncthreads();

    // ---- octx: C[64,64] = EA @ M^T; warp tile 32 rows x 16 cols ----
    float cx[2][2][4];
    {
        float cacc[2][2][4];
        #pragma unroll
        for (int i = 0; i < 2; i++)
            #pragma unroll
            for (int j = 0; j < 2; j++)
                #pragma unroll
                for (int q = 0; q < 4; q++) cacc[i][j][q] = 0.f;
        for (int ks = 0; ks < KVd; ks += 8) {
            uint32_t a[2][4], bb[2][2];
            #pragma unroll
            for (int i = 0; i < 2; i++) {
                int r0 = wr*32 + i*16;
                a[i][0] = bits(sEA[(r0+gid)*196 + ks+tig]);
                a[i][1] = bits(sEA[(r0+8+gid)*196 + ks+tig]);
                a[i][2] = bits(sEA[(r0+gid)*196 + ks+tig+4]);
                a[i][3] = bits(sEA[(r0+8+gid)*196 + ks+tig+4]);
            }
            #pragma unroll
            for (int j = 0; j < 2; j++) {
                int c0 = wc*16 + j*8;
                bb[j][0] = bits(__ldg(Mb + (c0+gid)*KVd + ks+tig));
                bb[j][1] = bits(__ldg(Mb + (c0+gid)*KVd + ks+tig+4));
            }
            #pragma unroll
            for (int i = 0; i < 2; i++)
                #pragma unroll
                for (int j = 0; j < 2; j++)
                    mma_tf32(cacc[i][j], a[i], bb[j]);
        }
        #pragma unroll
        for (int i = 0; i < 2; i++) {
            int r_lo = wr*32 + i*16 + gid, r_hi = r_lo + 8;
            #pragma unroll
            for (int j = 0; j < 2; j++) {
                int c0 = wc*16 + j*8 + 2*tig;
                float2 e0 = *(const float2*)(emb1 + (size_t)(base+r_lo)*C1d + c0);
                float2 e1 = *(const float2*)(emb1 + (size_t)(base+r_hi)*C1d + c0);
                cx[i][j][0] = cacc[i][j][0] + e0.x;
                cx[i][j][1] = cacc[i][j][1] + e0.y;
                cx[i][j][2] = cacc[i][j][2] + e1.x;
                cx[i][j][3] = cacc[i][j][3] + e1.y;
                *(float2*)(Xn + r_lo*68 + c0) = make_float2(cx[i][j][0], cx[i][j][1]);
                *(float2*)(Xn + r_hi*68 + c0) = make_float2(cx[i][j][2], cx[i][j][3]);
            }
        }
    }
    __syncthreads();
    if (tid < 64) {
        float s = 0.f, q = 0.f;
        const float* row = Xn + tid*68;
        #pragma unroll 8
        for (int c = 0; c < C1d; c++) { float v = row[c]; s += v; q += v*v; }
        float m = s * (1.f/C1d);
        float v = q * (1.f/C1d) - m*m;
        ms[tid] = m; rss[tid] = rsqrtf(v + 1e-6f);
    }
    __syncthreads();
    for (int i = tid; i < 64*C1d; i += 256) {
        int r = i >> 6, c = i & 63;
        Xn[r*68 + c] = (Xn[r*68 + c] - ms[r]) * rss[r] * __ldg(fg + c) + __ldg(fb + c);
    }
    __syncthreads();

    // ---- fc1 + gelu: H[64,256] = Xn @ W1^T; warp tile 32 rows x 64 cols ----
    {
        float h[2][8][4];
        #pragma unroll
        for (int i = 0; i < 2; i++)
            #pragma unroll
            for (int j = 0; j < 8; j++)
                #pragma unroll
                for (int q = 0; q < 4; q++) h[i][j][q] = 0.f;
        for (int ks = 0; ks < C1d; ks += 8) {
            uint32_t a[2][4], bb[8][2];
            #pragma unroll
            for (int i = 0; i < 2; i++) {
                int r0 = wr*32 + i*16;
                a[i][0] = bits(Xn[(r0+gid)*68 + ks+tig]);
                a[i][1] = bits(Xn[(r0+8+gid)*68 + ks+tig]);
                a[i][2] = bits(Xn[(r0+gid)*68 + ks+tig+4]);
                a[i][3] = bits(Xn[(r0+8+gid)*68 + ks+tig+4]);
            }
            #pragma unroll
            for (int j = 0; j < 8; j++) {
                int c0 = wc*64 + j*8;
                bb[j][0] = bits(__ldg(fc1w + (c0+gid)*C1d + ks+tig));
                bb[j][1] = bits(__ldg(fc1w + (c0+gid)*C1d + ks+tig+4));
            }
            #pragma unroll
            for (int i = 0; i < 2; i++)
                #pragma unroll
                for (int j = 0; j < 8; j++)
                    mma_tf32(h[i][j], a[i], bb[j]);
        }
        __syncthreads();
        #pragma unroll
        for (int i = 0; i < 2; i++) {
            int r_lo = wr*32 + i*16 + gid, r_hi = r_lo + 8;
            #pragma unroll
            for (int j = 0; j < 8; j++) {
                int c0 = wc*64 + j*8 + 2*tig;
                float2 bj = *(const float2*)(fc1b + c0);
                *(float2*)(Hs + r_lo*260 + c0) =
                    make_float2(gelu_exact(h[i][j][0] + bj.x), gelu_exact(h[i][j][1] + bj.y));
                *(float2*)(Hs + r_hi*260 + c0) =
                    make_float2(gelu_exact(h[i][j][2] + bj.x), gelu_exact(h[i][j][3] + bj.y));
            }
        }
    }
    __syncthreads();

    // ---- fc2 + bias + residual ----
    {
        float oacc[2][2][4];
        #pragma unroll
        for (int i = 0; i < 2; i++)
            #pragma unroll
            for (int j = 0; j < 2; j++)
                #pragma unroll
                for (int q = 0; q < 4; q++) oacc[i][j][q] = 0.f;
        for (int ks = 0; ks < MLPd; ks += 8) {
            uint32_t a[2][4], bb[2][2];
            #pragma unroll
            for (int i = 0; i < 2; i++) {
                int r0 = wr*32 + i*16;
                a[i][0] = bits(Hs[(r0+gid)*260 + ks+tig]);
                a[i][1] = bits(Hs[(r0+8+gid)*260 + ks+tig]);
                a[i][2] = bits(Hs[(r0+gid)*260 + ks+tig+4]);
                a[i][3] = bits(Hs[(r0+8+gid)*260 + ks+tig+4]);
            }
            #pragma unroll
            for (int j = 0; j < 2; j++) {
                int c0 = wc*16 + j*8;
                bb[j][0] = bits(__ldg(fc2w + (c0+gid)*MLPd + ks+tig));
                bb[j][1] = bits(__ldg(fc2w + (c0+gid)*MLPd + ks+tig+4));
            }
            #pragma unroll
            for (int i = 0; i < 2; i++)
                #pragma unroll
                for (int j = 0; j < 2; j++)
                    mma_tf32(oacc[i][j], a[i], bb[j]);
        }
        #pragma unroll
        for (int i = 0; i < 2; i++) {
            int r_lo = wr*32 + i*16 + gid, r_hi = r_lo + 8;
            #pragma unroll
            for (int j = 0; j < 2; j++) {
                int c0 = wc*16 + j*8 + 2*tig;
                float2 b2 = *(const float2*)(fc2b + c0);
                float2 o0, o1;
                o0.x = oacc[i][j][0] + b2.x + cx[i][j][0];
                o0.y = oacc[i][j][1] + b2.y + cx[i][j][1];
                o1.x = oacc[i][j][2] + b2.x + cx[i][j][2];
                o1.y = oacc[i][j][3] + b2.y + cx[i][j][3];
                *(float2*)(out + (size_t)(base+r_lo)*C1d + c0) = o0;
                *(float2*)(out + (size_t)(base+r_hi)*C1d + c0) = o1;
            }
        }
    }
}

// ---------------- launch ----------------
extern "C" void kernel_launch(void* const* d_in, const int* in_sizes, int n_in,
                              void* d_out, int out_size) {
    const float* emb1   = (const float*)d_in[0];
    const float* emb2   = (const float*)d_in[1];
    const float* Wq     = (const float*)d_in[2];
    const float* Wk     = (const float*)d_in[3];
    const float* Wv     = (const float*)d_in[4];
    const float* Wout   = (const float*)d_in[5];
    const float* ln1_g  = (const float*)d_in[6];
    const float* ln1_b  = (const float*)d_in[7];
    const float* lnA_g  = (const float*)d_in[8];
    const float* lnA_b  = (const float*)d_in[9];
    const float* ffn_g  = (const float*)d_in[10];
    const float* ffn_b  = (const float*)d_in[11];
    const float* fc1_w  = (const float*)d_in[12];
    const float* fc1_b  = (const float*)d_in[13];
    const float* fc2_w  = (const float*)d_in[14];
    const float* fc2_b  = (const float*)d_in[15];
    float* out = (float*)d_out;

    const int smem_gmatln = (64*196 + 64*65) * 4;                    // 66816
    const int smem_smatT  = (64*196 + 64*196 + 64*68 + 192*52) * 4;  // 157696
    const int smem_pmat   = (64*196 + 192*52) * 4;                   // 90112
    const int smem_mmat   = (64*52 + 64*68) * 4;                     // 30720
    const int smem_tail   = T_TOT * 4;                               // 83968

    cudaFuncSetAttribute(gmatln_kernel, cudaFuncAttributeMaxDynamicSharedMemorySize, smem_gmatln);
    cudaFuncSetAttribute(smatT_kernel,  cudaFuncAttributeMaxDynamicSharedMemorySize, smem_smatT);
    cudaFuncSetAttribute(pmat_kernel,   cudaFuncAttributeMaxDynamicSharedMemorySize, smem_pmat);
    cudaFuncSetAttribute(mmat_kernel,   cudaFuncAttributeMaxDynamicSharedMemorySize, smem_mmat);
    cudaFuncSetAttribute(tail_kernel,   cudaFuncAttributeMaxDynamicSharedMemorySize, smem_tail);

    init_kernel<<<(Bq*GSZ)/256, 256>>>();
    gmatln_kernel<<<dim3(NCH, Bq), 256, smem_gmatln>>>(emb1, emb2, ln1_g, ln1_b, lnA_g, lnA_b);
    smatT_kernel<<<dim3(Bq*Hh, 4), 256, smem_smatT>>>(Wq, Wk);
    pmat_kernel<<<dim3(Bq*Hh, 4), 256, smem_pmat>>>(Wv);
    mmat_kernel<<<dim3(Bq, 4), 128, smem_mmat>>>(Wout);
    tail_kernel<<<dim3(NCH, Bq), 256, smem_tail>>>(emb1, fc1_w, fc2_w, fc1_b, fc2_b, ffn_g, ffn_b, out);
}

// round 13
// speedup vs baseline: 1.5178x; 1.0356x over previous
#include <cuda_runtime.h>
#include <math.h>
#include <stdint.h>

#define Bq   8
#define Nn   3136
#define C1d  64
#define C2d  128
#define KVd  192
#define Hh   4
#define MLPd 256
#define NROW (Bq*Nn)     /* 25088 */
#define NCH  49          /* 3136 / 64 */
#define GSZ  (C1d*KVd)   /* 12288 */

// ---------------- scratch (device globals; no allocation) ----------------
__device__ float g_ea[NROW*KVd];          // LN(concat) rows (fp32; mma truncates)
__device__ float g_G[Bq*GSZ];             // fp32 atomic-accumulated G
__device__ float g_S[Bq*Hh*GSZ];          // scores (scaled, pre-IN, fp32)
__device__ float2 g_pstats[Bq*Hh*4];      // per-tile (sum, sumsq) of scores
__device__ float g_M[Bq*GSZ];             // fp32 atomic-accumulated M

extern __shared__ float dsm[];

__device__ __forceinline__ uint32_t bits(float f) { return __float_as_uint(f); }
// mma reads the top 19 bits of each operand -> fp32 bits act as RZ-truncated tf32
__device__ __forceinline__ void mma_tf32(float* c, const uint32_t* a, const uint32_t* b) {
    asm volatile("mma.sync.aligned.m16n8k8.row.col.f32.tf32.tf32.f32 "
        "{%0,%1,%2,%3}, {%4,%5,%6,%7}, {%8,%9}, {%0,%1,%2,%3};"
        : "+f"(c[0]), "+f"(c[1]), "+f"(c[2]), "+f"(c[3])
        : "r"(a[0]), "r"(a[1]), "r"(a[2]), "r"(a[3]), "r"(b[0]), "r"(b[1]));
}

// ============ 0) init: zero g_G and g_M ============
__global__ void init_kernel() {
    int idx = blockIdx.x*256 + threadIdx.x;
    g_G[idx] = 0.f;
    g_M[idx] = 0.f;
}

// ============ 1) fused dual-LayerNorm + G partial -> atomicAdd into g_G =====
// grid (49, 8), 256 threads
__global__ __launch_bounds__(256,2) void gmatln_kernel(
        const float* __restrict__ emb1, const float* __restrict__ emb2,
        const float* __restrict__ g1, const float* __restrict__ b1,
        const float* __restrict__ gA, const float* __restrict__ bA) {
    float* sE = dsm;                 // [64][196] raw -> ea
    float* sC = dsm + 64*196;        // [64][65]  cx1
    __shared__ float m1s[64], r1s[64], mAs[64], rAs[64];
    int ch = blockIdx.x, b = blockIdx.y;
    int base = b*Nn + ch*64;
    int tid = threadIdx.x;
    for (int i = tid; i < 64*48; i += 256) {
        int r = i / 48, c = (i % 48)*4;
        float4 v = (c < C1d) ? *(const float4*)(emb1 + (size_t)(base+r)*C1d + c)
                             : *(const float4*)(emb2 + (size_t)(base+r)*C2d + (c - C1d));
        *(float4*)(sE + r*196 + c) = v;
    }
    __syncthreads();
    if (tid < 64) {
        float s1 = 0.f, q1 = 0.f, s2 = 0.f, q2 = 0.f;
        const float* row = sE + tid*196;
        #pragma unroll 8
        for (int c = 0; c < C1d; c++)  { float v = row[c]; s1 += v; q1 += v*v; }
        #pragma unroll 8
        for (int c = C1d; c < KVd; c++){ float v = row[c]; s2 += v; q2 += v*v; }
        float m1 = s1 * (1.f/C1d);
        float v1 = q1 * (1.f/C1d) - m1*m1;
        m1s[tid] = m1; r1s[tid] = rsqrtf(v1 + 1e-6f);
        float mA = (s1+s2) * (1.f/KVd);
        float vA = (q1+q2) * (1.f/KVd) - mA*mA;
        mAs[tid] = mA; rAs[tid] = rsqrtf(vA + 1e-6f);
    }
    __syncthreads();
    for (int i = tid; i < 64*48; i += 256) {
        int r = i / 48, c = (i % 48)*4;
        float4 v = *(const float4*)(sE + r*196 + c);
        float4 g = *(const float4*)(gA + c);
        float4 bb4 = *(const float4*)(bA + c);
        float mA = mAs[r], rA = rAs[r];
        float4 ea;
        ea.x = (v.x - mA)*rA*g.x + bb4.x;
        ea.y = (v.y - mA)*rA*g.y + bb4.y;
        ea.z = (v.z - mA)*rA*g.z + bb4.z;
        ea.w = (v.w - mA)*rA*g.w + bb4.w;
        *(float4*)(sE + r*196 + c) = ea;
        *(float4*)(g_ea + (size_t)(base+r)*KVd + c) = ea;
        if (c < C1d) {
            float m1 = m1s[r], r1 = r1s[r];
            sC[r*65 + c+0] = (v.x - m1)*r1*__ldg(g1 + c+0) + __ldg(b1 + c+0);
            sC[r*65 + c+1] = (v.y - m1)*r1*__ldg(g1 + c+1) + __ldg(b1 + c+1);
            sC[r*65 + c+2] = (v.z - m1)*r1*__ldg(g1 + c+2) + __ldg(b1 + c+2);
            sC[r*65 + c+3] = (v.w - m1)*r1*__ldg(g1 + c+3) + __ldg(b1 + c+3);
        }
    }
    __syncthreads();
    int w = tid >> 5, lane = tid & 31;
    int gid = lane >> 2, tig = lane & 3;
    int wr = w >> 2, wc = w & 3;       // 2 x 4 warps; tile 32m x 48n
    float cacc[2][6][4];
    #pragma unroll
    for (int i = 0; i < 2; i++)
        #pragma unroll
        for (int j = 0; j < 6; j++)
            #pragma unroll
            for (int q = 0; q < 4; q++) cacc[i][j][q] = 0.f;
    for (int ks = 0; ks < C1d; ks += 8) {
        uint32_t a[2][4], bb[6][2];
        #pragma unroll
        for (int i = 0; i < 2; i++) {
            int m0 = wr*32 + i*16;
            a[i][0] = bits(sC[(ks+tig)*65 + m0+gid]);
            a[i][1] = bits(sC[(ks+tig)*65 + m0+8+gid]);
            a[i][2] = bits(sC[(ks+tig+4)*65 + m0+gid]);
            a[i][3] = bits(sC[(ks+tig+4)*65 + m0+8+gid]);
        }
        #pragma unroll
        for (int j = 0; j < 6; j++) {
            int n0 = wc*48 + j*8;
            bb[j][0] = bits(sE[(ks+tig)*196 + n0+gid]);
            bb[j][1] = bits(sE[(ks+tig+4)*196 + n0+gid]);
        }
        #pragma unroll
        for (int i = 0; i < 2; i++)
            #pragma unroll
            for (int j = 0; j < 6; j++)
                mma_tf32(cacc[i][j], a[i], bb[j]);
    }
    float* out = g_G + (size_t)b*GSZ;
    #pragma unroll
    for (int i = 0; i < 2; i++) {
        int r_lo = wr*32 + i*16 + gid, r_hi = r_lo + 8;
        #pragma unroll
        for (int j = 0; j < 6; j++) {
            int c0 = wc*48 + j*8 + 2*tig;
            atomicAdd(out + r_lo*KVd + c0,     cacc[i][j][0]);
            atomicAdd(out + r_lo*KVd + c0 + 1, cacc[i][j][1]);
            atomicAdd(out + r_hi*KVd + c0,     cacc[i][j][2]);
            atomicAdd(out + r_hi*KVd + c0 + 1, cacc[i][j][3]);
        }
    }
}

// ============ 2) fused T=Wq@G, S = T@Wk^T/sqrt(KV) + partial stats =====
// grid (32, 4), 256 threads
__global__ __launch_bounds__(256,1) void smatT_kernel(
        const float* __restrict__ Wq, const float* __restrict__ Wk) {
    float* sG  = dsm;                  // [64][196]
    float* sT  = dsm + 64*196;         // [64][196]
    float* sWq = sT + 64*196;          // [64][68]   Wq row-major
    float* sWk = sWq + 64*68;          // [192][52]  Wk^T tile
    __shared__ float redS[8], redQ[8];
    int bh = blockIdx.x, tile = blockIdx.y;
    int b = bh >> 2, h = bh & 3;
    int tid = threadIdx.x;
    for (int i = tid; i < 64*48; i += 256) {
        int c = i / 48, k = (i % 48)*4;
        *(float4*)(sG + c*196 + k) = *(const float4*)(g_G + (size_t)b*GSZ + c*KVd + k);
    }
    for (int i = tid; i < 1024; i += 256) {
        int d = i >> 4, c = (i & 15)*4;
        *(float4*)(sWq + d*68 + c) = *(const float4*)(Wq + (size_t)h*C1d*C1d + d*C1d + c);
    }
    for (int i = tid; i < 48*48; i += 256) {
        int j = i / 48, kp = (i % 48)*4;
        float4 v = *(const float4*)(Wk + (size_t)h*KVd*KVd + (tile*48 + j)*KVd + kp);
        sWk[(kp+0)*52 + j] = v.x;
        sWk[(kp+1)*52 + j] = v.y;
        sWk[(kp+2)*52 + j] = v.z;
        sWk[(kp+3)*52 + j] = v.w;
    }
    __syncthreads();
    int w = tid >> 5, lane = tid & 31;
    int gid = lane >> 2, tig = lane & 3;
    // Phase 1: T = Wq @ G  (m=64, n=192, k=64); warps 2x4, tile 32x48
    {
        int wr = w >> 2, wc = w & 3;
        float cacc[2][6][4];
        #pragma unroll
        for (int i = 0; i < 2; i++)
            #pragma unroll
            for (int j = 0; j < 6; j++)
                #pragma unroll
                for (int q = 0; q < 4; q++) cacc[i][j][q] = 0.f;
        for (int ks = 0; ks < C1d; ks += 8) {
            uint32_t a[2][4], bb[6][2];
            #pragma unroll
            for (int i = 0; i < 2; i++) {
                int m0 = wr*32 + i*16;
                a[i][0] = bits(sWq[(m0+gid)*68 + ks+tig]);
                a[i][1] = bits(sWq[(m0+8+gid)*68 + ks+tig]);
                a[i][2] = bits(sWq[(m0+gid)*68 + ks+tig+4]);
                a[i][3] = bits(sWq[(m0+8+gid)*68 + ks+tig+4]);
            }
            #pragma unroll
            for (int j = 0; j < 6; j++) {
                int n0 = wc*48 + j*8;
                bb[j][0] = bits(sG[(ks+tig)*196 + n0+gid]);
                bb[j][1] = bits(sG[(ks+tig+4)*196 + n0+gid]);
            }
            #pragma unroll
            for (int i = 0; i < 2; i++)
                #pragma unroll
                for (int j = 0; j < 6; j++)
                    mma_tf32(cacc[i][j], a[i], bb[j]);
        }
        #pragma unroll
        for (int i = 0; i < 2; i++) {
            int r_lo = wr*32 + i*16 + gid, r_hi = r_lo + 8;
            #pragma unroll
            for (int j = 0; j < 6; j++) {
                int c0 = wc*48 + j*8 + 2*tig;
                *(float2*)(sT + r_lo*196 + c0) = make_float2(cacc[i][j][0], cacc[i][j][1]);
                *(float2*)(sT + r_hi*196 + c0) = make_float2(cacc[i][j][2], cacc[i][j][3]);
            }
        }
    }
    __syncthreads();
    // Phase 2: S = T @ Wk^T * scale  (m=64, n=48, k=192); warps 4x2, tile 16x24
    const float scale = 0.0721687836487f;   // 1/sqrt(192)
    float lsum = 0.f, lsq = 0.f;
    {
        int wr = w >> 1, wc = w & 1;
        int m0 = wr*16, n0 = wc*24;
        float cacc[3][4];
        #pragma unroll
        for (int j = 0; j < 3; j++)
            #pragma unroll
            for (int q = 0; q < 4; q++) cacc[j][q] = 0.f;
        uint32_t a[2][4], bb[2][3][2];
        a[0][0] = bits(sT[(m0+gid)*196 + tig]);
        a[0][1] = bits(sT[(m0+8+gid)*196 + tig]);
        a[0][2] = bits(sT[(m0+gid)*196 + tig+4]);
        a[0][3] = bits(sT[(m0+8+gid)*196 + tig+4]);
        #pragma unroll
        for (int j = 0; j < 3; j++) {
            int c0 = n0 + j*8;
            bb[0][j][0] = bits(sWk[(tig)*52 + c0+gid]);
            bb[0][j][1] = bits(sWk[(tig+4)*52 + c0+gid]);
        }
        #pragma unroll
        for (int it = 0; it < 24; it++) {
            int cur = it & 1, nxt = cur ^ 1;
            int ksn = (it+1)*8;
            if (it < 23) {
                a[nxt][0] = bits(sT[(m0+gid)*196 + ksn+tig]);
                a[nxt][1] = bits(sT[(m0+8+gid)*196 + ksn+tig]);
                a[nxt][2] = bits(sT[(m0+gid)*196 + ksn+tig+4]);
                a[nxt][3] = bits(sT[(m0+8+gid)*196 + ksn+tig+4]);
                #pragma unroll
                for (int j = 0; j < 3; j++) {
                    int c0 = n0 + j*8;
                    bb[nxt][j][0] = bits(sWk[(ksn+tig)*52 + c0+gid]);
                    bb[nxt][j][1] = bits(sWk[(ksn+tig+4)*52 + c0+gid]);
                }
            }
            #pragma unroll
            for (int j = 0; j < 3; j++)
                mma_tf32(cacc[j], a[cur], bb[cur][j]);
        }
        float* out = g_S + (size_t)bh*GSZ;
        int r_lo = m0 + gid, r_hi = r_lo + 8;
        #pragma unroll
        for (int j = 0; j < 3; j++) {
            int c0 = tile*48 + n0 + j*8 + 2*tig;
            float v0 = cacc[j][0]*scale, v1 = cacc[j][1]*scale;
            float v2 = cacc[j][2]*scale, v3 = cacc[j][3]*scale;
            *(float2*)(out + r_lo*KVd + c0) = make_float2(v0, v1);
            *(float2*)(out + r_hi*KVd + c0) = make_float2(v2, v3);
            lsum += v0+v1+v2+v3;
            lsq  += v0*v0+v1*v1+v2*v2+v3*v3;
        }
    }
    #pragma unroll
    for (int o = 16; o > 0; o >>= 1) {
        lsum += __shfl_down_sync(0xffffffffu, lsum, o);
        lsq  += __shfl_down_sync(0xffffffffu, lsq, o);
    }
    if (lane == 0) { redS[w] = lsum; redQ[w] = lsq; }
    __syncthreads();
    if (tid == 0) {
        float s = 0.f, q = 0.f;
        #pragma unroll
        for (int i = 0; i < 8; i++) { s += redS[i]; q += redQ[i]; }
        g_pstats[bh*4 + tile] = make_float2(s, q);
    }
}

// ============ 3) fused IN + softmax + Pp = probs@Wv + M += Wout@Pp/4 ========
// grid (32, 4), 256 threads
__global__ __launch_bounds__(256,1) void pmatM_kernel(
        const float* __restrict__ Wv, const float* __restrict__ Wout) {
    float* sS  = dsm;                          // [64][196] scores -> probs
    float* sV  = dsm + 64*196;                 // [192][52] Wv tile
    float* sW  = sV + 192*52;                  // [64][68]  Wout row-major
    float* sPp = sW + 64*68;                   // [64][52]  Pp tile
    __shared__ float s_m, s_rs;
    int bh = blockIdx.x, h = bh & 3, tile = blockIdx.y;
    int b = bh >> 2;
    int tid = threadIdx.x;
    for (int i = tid; i < 64*48; i += 256) {
        int c = i / 48, k = (i % 48)*4;
        *(float4*)(sS + c*196 + k) = *(const float4*)(g_S + (size_t)bh*GSZ + c*KVd + k);
    }
    for (int i = tid; i < 192*12; i += 256) {
        int k = i / 12, c = (i % 12)*4;
        *(float4*)(sV + k*52 + c) = *(const float4*)(Wv + (size_t)h*KVd*KVd + k*KVd + tile*48 + c);
    }
    for (int i = tid; i < 1024; i += 256) {
        int d = i >> 4, c = (i & 15)*4;
        *(float4*)(sW + d*68 + c) = *(const float4*)(Wout + d*C1d + c);
    }
    if (tid == 0) {
        float s = 0.f, q = 0.f;
        #pragma unroll
        for (int t = 0; t < 4; t++) {
            float2 p = g_pstats[bh*4 + t];
            s += p.x; q += p.y;
        }
        float m = s * (1.f/GSZ);
        float v = q * (1.f/GSZ) - m*m;
        s_m = m; s_rs = rsqrtf(v + 1e-5f);
    }
    __syncthreads();
    float mean = s_m, rs = s_rs;
    int w = tid >> 5, lane = tid & 31;
    for (int r = w; r < C1d; r += 8) {
        float vals[6];
        float mx = -1e30f;
        #pragma unroll
        for (int mm = 0; mm < 6; mm++) {
            vals[mm] = (sS[r*196 + lane + 32*mm] - mean) * rs;
            mx = fmaxf(mx, vals[mm]);
        }
        #pragma unroll
        for (int o = 16; o > 0; o >>= 1) mx = fmaxf(mx, __shfl_xor_sync(0xffffffffu, mx, o));
        float es = 0.f;
        #pragma unroll
        for (int mm = 0; mm < 6; mm++) { vals[mm] = __expf(vals[mm] - mx); es += vals[mm]; }
        #pragma unroll
        for (int o = 16; o > 0; o >>= 1) es += __shfl_xor_sync(0xffffffffu, es, o);
        float inv = 1.f / es;
        #pragma unroll
        for (int mm = 0; mm < 6; mm++) sS[r*196 + lane + 32*mm] = vals[mm] * inv;
    }
    __syncthreads();
    // GEMM1: Pp = probs @ Wv  (m=64, n=48, k=192); warps 4x2, tile 16x24; dbl-buf
    int gid = lane >> 2, tig = lane & 3;
    int wr = w >> 1, wc = w & 1;
    int m0 = wr*16, n0 = wc*24;
    {
        float cacc[3][4];
        #pragma unroll
        for (int j = 0; j < 3; j++)
            #pragma unroll
            for (int q = 0; q < 4; q++) cacc[j][q] = 0.f;
        uint32_t a[2][4], bb[2][3][2];
        a[0][0] = bits(sS[(m0+gid)*196 + tig]);
        a[0][1] = bits(sS[(m0+8+gid)*196 + tig]);
        a[0][2] = bits(sS[(m0+gid)*196 + tig+4]);
        a[0][3] = bits(sS[(m0+8+gid)*196 + tig+4]);
        #pragma unroll
        for (int j = 0; j < 3; j++) {
            int c0 = n0 + j*8;
            bb[0][j][0] = bits(sV[(tig)*52 + c0+gid]);
            bb[0][j][1] = bits(sV[(tig+4)*52 + c0+gid]);
        }
        #pragma unroll
        for (int it = 0; it < 24; it++) {
            int cur = it & 1, nxt = cur ^ 1;
            int ksn = (it+1)*8;
            if (it < 23) {
                a[nxt][0] = bits(sS[(m0+gid)*196 + ksn+tig]);
                a[nxt][1] = bits(sS[(m0+8+gid)*196 + ksn+tig]);
                a[nxt][2] = bits(sS[(m0+gid)*196 + ksn+tig+4]);
                a[nxt][3] = bits(sS[(m0+8+gid)*196 + ksn+tig+4]);
                #pragma unroll
                for (int j = 0; j < 3; j++) {
                    int c0 = n0 + j*8;
                    bb[nxt][j][0] = bits(sV[(ksn+tig)*52 + c0+gid]);
                    bb[nxt][j][1] = bits(sV[(ksn+tig+4)*52 + c0+gid]);
                }
            }
            #pragma unroll
            for (int j = 0; j < 3; j++)
                mma_tf32(cacc[j], a[cur], bb[cur][j]);
        }
        int r_lo = m0 + gid, r_hi = r_lo + 8;
        #pragma unroll
        for (int j = 0; j < 3; j++) {
            int c0 = n0 + j*8 + 2*tig;
            *(float2*)(sPp + r_lo*52 + c0) = make_float2(cacc[j][0], cacc[j][1]);
            *(float2*)(sPp + r_hi*52 + c0) = make_float2(cacc[j][2], cacc[j][3]);
        }
    }
    __syncthreads();
    // GEMM2: M_tile = Wout @ Pp  (m=64 d, n=48, k=64 c); warps 4x2, tile 16x24
    {
        float macc[3][4];
        #pragma unroll
        for (int j = 0; j < 3; j++)
            #pragma unroll
            for (int q = 0; q < 4; q++) macc[j][q] = 0.f;
        for (int ks = 0; ks < C1d; ks += 8) {
            uint32_t a[4], bb[3][2];
            a[0] = bits(sW[(m0+gid)*68 + ks+tig]);
            a[1] = bits(sW[(m0+8+gid)*68 + ks+tig]);
            a[2] = bits(sW[(m0+gid)*68 + ks+tig+4]);
            a[3] = bits(sW[(m0+8+gid)*68 + ks+tig+4]);
            #pragma unroll
            for (int j = 0; j < 3; j++) {
                int c0 = n0 + j*8;
                bb[j][0] = bits(sPp[(ks+tig)*52 + c0+gid]);
                bb[j][1] = bits(sPp[(ks+tig+4)*52 + c0+gid]);
            }
            #pragma unroll
            for (int j = 0; j < 3; j++)
                mma_tf32(macc[j], a, bb[j]);
        }
        float* outM = g_M + (size_t)b*GSZ;
        int r_lo = m0 + gid, r_hi = r_lo + 8;
        #pragma unroll
        for (int j = 0; j < 3; j++) {
            int c0 = tile*48 + n0 + j*8 + 2*tig;
            atomicAdd(outM + r_lo*KVd + c0,     macc[j][0]*0.25f);
            atomicAdd(outM + r_lo*KVd + c0 + 1, macc[j][1]*0.25f);
            atomicAdd(outM + r_hi*KVd + c0,     macc[j][2]*0.25f);
            atomicAdd(outM + r_hi*KVd + c0 + 1, macc[j][3]*0.25f);
        }
    }
}

// ============ 4) fused tail (tf32 mma, raw fp32 operands) ======
__device__ __forceinline__ float gelu_exact(float x) {
    return 0.5f * x * (1.f + erff(x * 0.70710678118654752f));
}

#define T_HS   0                      /* Hs [64][260]=16640 ; alias sEA [64][196]=12544 */
#define T_XN   16640                  /* Xn [64][68] =4352  */
#define T_TOT  20992                  /* *4 = 83968 B */

__global__ __launch_bounds__(256,2) void tail_kernel(
        const float* __restrict__ emb1,
        const float* __restrict__ fc1w, const float* __restrict__ fc2w,
        const float* __restrict__ fc1b, const float* __restrict__ fc2b,
        const float* __restrict__ fg, const float* __restrict__ fb,
        float* __restrict__ out) {
    float* sEA = dsm + T_HS;           // [64][196]
    float* Hs  = dsm + T_HS;           // [64][260]  (after octx)
    float* Xn  = dsm + T_XN;           // [64][68]
    __shared__ float ms[64], rss[64];
    int ch = blockIdx.x, b = blockIdx.y;
    int base = b*Nn + ch*64;
    int tid = threadIdx.x;
    int w = tid >> 5, lane = tid & 31;
    int gid = lane >> 2, tig = lane & 3;
    int wr = w >> 2, wc = w & 3;       // warp grid 2 x 4
    const float* Mb = g_M + (size_t)b*GSZ;

    for (int i = tid; i < 64*48; i += 256) {
        int r = i / 48, k = (i % 48)*4;
        *(float4*)(sEA + r*196 + k) = *(const float4*)(g_ea + (size_t)base*KVd + r*KVd + k);
    }
    __syncthreads();

    // ---- octx: C[64,64] = EA @ M^T; warp tile 32 rows x 16 cols ----
    float cx[2][2][4];
    {
        float cacc[2][2][4];
        #pragma unroll
        for (int i = 0; i < 2; i++)
            #pragma unroll
            for (int j = 0; j < 2; j++)
                #pragma unroll
                for (int q = 0; q < 4; q++) cacc[i][j][q] = 0.f;
        for (int ks = 0; ks < KVd; ks += 8) {
            uint32_t a[2][4], bb[2][2];
            #pragma unroll
            for (int i = 0; i < 2; i++) {
                int r0 = wr*32 + i*16;
                a[i][0] = bits(sEA[(r0+gid)*196 + ks+tig]);
                a[i][1] = bits(sEA[(r0+8+gid)*196 + ks+tig]);
                a[i][2] = bits(sEA[(r0+gid)*196 + ks+tig+4]);
                a[i][3] = bits(sEA[(r0+8+gid)*196 + ks+tig+4]);
            }
            #pragma unroll
            for (int j = 0; j < 2; j++) {
                int c0 = wc*16 + j*8;
                bb[j][0] = bits(__ldg(Mb + (c0+gid)*KVd + ks+tig));
                bb[j][1] = bits(__ldg(Mb + (c0+gid)*KVd + ks+tig+4));
            }
            #pragma unroll
            for (int i = 0; i < 2; i++)
                #pragma unroll
                for (int j = 0; j < 2; j++)
                    mma_tf32(cacc[i][j], a[i], bb[j]);
        }
        #pragma unroll
        for (int i = 0; i < 2; i++) {
            int r_lo = wr*32 + i*16 + gid, r_hi = r_lo + 8;
            #pragma unroll
            for (int j = 0; j < 2; j++) {
                int c0 = wc*16 + j*8 + 2*tig;
                float2 e0 = *(const float2*)(emb1 + (size_t)(base+r_lo)*C1d + c0);
                float2 e1 = *(const float2*)(emb1 + (size_t)(base+r_hi)*C1d + c0);
                cx[i][j][0] = cacc[i][j][0] + e0.x;
                cx[i][j][1] = cacc[i][j][1] + e0.y;
                cx[i][j][2] = cacc[i][j][2] + e1.x;
                cx[i][j][3] = cacc[i][j][3] + e1.y;
                *(float2*)(Xn + r_lo*68 + c0) = make_float2(cx[i][j][0], cx[i][j][1]);
                *(float2*)(Xn + r_hi*68 + c0) = make_float2(cx[i][j][2], cx[i][j][3]);
            }
        }
    }
    __syncthreads();
    if (tid < 64) {
        float s = 0.f, q = 0.f;
        const float* row = Xn + tid*68;
        #pragma unroll 8
        for (int c = 0; c < C1d; c++) { float v = row[c]; s += v; q += v*v; }
        float m = s * (1.f/C1d);
        float v = q * (1.f/C1d) - m*m;
        ms[tid] = m; rss[tid] = rsqrtf(v + 1e-6f);
    }
    __syncthreads();
    for (int i = tid; i < 64*C1d; i += 256) {
        int r = i >> 6, c = i & 63;
        Xn[r*68 + c] = (Xn[r*68 + c] - ms[r]) * rss[r] * __ldg(fg + c) + __ldg(fb + c);
    }
    __syncthreads();

    // ---- fc1 + gelu: H[64,256] = Xn @ W1^T; warp tile 32 rows x 64 cols ----
    {
        float h[2][8][4];
        #pragma unroll
        for (int i = 0; i < 2; i++)
            #pragma unroll
            for (int j = 0; j < 8; j++)
                #pragma unroll
                for (int q = 0; q < 4; q++) h[i][j][q] = 0.f;
        for (int ks = 0; ks < C1d; ks += 8) {
            uint32_t a[2][4], bb[8][2];
            #pragma unroll
            for (int i = 0; i < 2; i++) {
                int r0 = wr*32 + i*16;
                a[i][0] = bits(Xn[(r0+gid)*68 + ks+tig]);
                a[i][1] = bits(Xn[(r0+8+gid)*68 + ks+tig]);
                a[i][2] = bits(Xn[(r0+gid)*68 + ks+tig+4]);
                a[i][3] = bits(Xn[(r0+8+gid)*68 + ks+tig+4]);
            }
            #pragma unroll
            for (int j = 0; j < 8; j++) {
                int c0 = wc*64 + j*8;
                bb[j][0] = bits(__ldg(fc1w + (c0+gid)*C1d + ks+tig));
                bb[j][1] = bits(__ldg(fc1w + (c0+gid)*C1d + ks+tig+4));
            }
            #pragma unroll
            for (int i = 0; i < 2; i++)
                #pragma unroll
                for (int j = 0; j < 8; j++)
                    mma_tf32(h[i][j], a[i], bb[j]);
        }
        __syncthreads();
        #pragma unroll
        for (int i = 0; i < 2; i++) {
            int r_lo = wr*32 + i*16 + gid, r_hi = r_lo + 8;
            #pragma unroll
            for (int j = 0; j < 8; j++) {
                int c0 = wc*64 + j*8 + 2*tig;
                float2 bj = *(const float2*)(fc1b + c0);
                *(float2*)(Hs + r_lo*260 + c0) =
                    make_float2(gelu_exact(h[i][j][0] + bj.x), gelu_exact(h[i][j][1] + bj.y));
                *(float2*)(Hs + r_hi*260 + c0) =
                    make_float2(gelu_exact(h[i][j][2] + bj.x), gelu_exact(h[i][j][3] + bj.y));
            }
        }
    }
    __syncthreads();

    // ---- fc2 + bias + residual ----
    {
        float oacc[2][2][4];
        #pragma unroll
        for (int i = 0; i < 2; i++)
            #pragma unroll
            for (int j = 0; j < 2; j++)
                #pragma unroll
                for (int q = 0; q < 4; q++) oacc[i][j][q] = 0.f;
        for (int ks = 0; ks < MLPd; ks += 8) {
            uint32_t a[2][4], bb[2][2];
            #pragma unroll
            for (int i = 0; i < 2; i++) {
                int r0 = wr*32 + i*16;
                a[i][0] = bits(Hs[(r0+gid)*260 + ks+tig]);
                a[i][1] = bits(Hs[(r0+8+gid)*260 + ks+tig]);
                a[i][2] = bits(Hs[(r0+gid)*260 + ks+tig+4]);
                a[i][3] = bits(Hs[(r0+8+gid)*260 + ks+tig+4]);
            }
            #pragma unroll
            for (int j = 0; j < 2; j++) {
                int c0 = wc*16 + j*8;
                bb[j][0] = bits(__ldg(fc2w + (c0+gid)*MLPd + ks+tig));
                bb[j][1] = bits(__ldg(fc2w + (c0+gid)*MLPd + ks+tig+4));
            }
            #pragma unroll
            for (int i = 0; i < 2; i++)
                #pragma unroll
                for (int j = 0; j < 2; j++)
                    mma_tf32(oacc[i][j], a[i], bb[j]);
        }
        #pragma unroll
        for (int i = 0; i < 2; i++) {
            int r_lo = wr*32 + i*16 + gid, r_hi = r_lo + 8;
            #pragma unroll
            for (int j = 0; j < 2; j++) {
                int c0 = wc*16 + j*8 + 2*tig;
                float2 b2 = *(const float2*)(fc2b + c0);
                float2 o0, o1;
                o0.x = oacc[i][j][0] + b2.x + cx[i][j][0];
                o0.y = oacc[i][j][1] + b2.y + cx[i][j][1];
                o1.x = oacc[i][j][2] + b2.x + cx[i][j][2];
                o1.y = oacc[i][j][3] + b2.y + cx[i][j][3];
                *(float2*)(out + (size_t)(base+r_lo)*C1d + c0) = o0;
                *(float2*)(out + (size_t)(base+r_hi)*C1d + c0) = o1;
            }
        }
    }
}

// ---------------- launch ----------------
extern "C" void kernel_launch(void* const* d_in, const int* in_sizes, int n_in,
                              void* d_out, int out_size) {
    const float* emb1   = (const float*)d_in[0];
    const float* emb2   = (const float*)d_in[1];
    const float* Wq     = (const float*)d_in[2];
    const float* Wk     = (const float*)d_in[3];
    const float* Wv     = (const float*)d_in[4];
    const float* Wout   = (const float*)d_in[5];
    const float* ln1_g  = (const float*)d_in[6];
    const float* ln1_b  = (const float*)d_in[7];
    const float* lnA_g  = (const float*)d_in[8];
    const float* lnA_b  = (const float*)d_in[9];
    const float* ffn_g  = (const float*)d_in[10];
    const float* ffn_b  = (const float*)d_in[11];
    const float* fc1_w  = (const float*)d_in[12];
    const float* fc1_b  = (const float*)d_in[13];
    const float* fc2_w  = (const float*)d_in[14];
    const float* fc2_b  = (const float*)d_in[15];
    float* out = (float*)d_out;

    const int smem_gmatln = (64*196 + 64*65) * 4;                    // 66816
    const int smem_smatT  = (64*196 + 64*196 + 64*68 + 192*52) * 4;  // 157696
    const int smem_pmatM  = (64*196 + 192*52 + 64*68 + 64*52) * 4;   // 120832
    const int smem_tail   = T_TOT * 4;                               // 83968

    cudaFuncSetAttribute(gmatln_kernel, cudaFuncAttributeMaxDynamicSharedMemorySize, smem_gmatln);
    cudaFuncSetAttribute(smatT_kernel,  cudaFuncAttributeMaxDynamicSharedMemorySize, smem_smatT);
    cudaFuncSetAttribute(pmatM_kernel,  cudaFuncAttributeMaxDynamicSharedMemorySize, smem_pmatM);
    cudaFuncSetAttribute(tail_kernel,   cudaFuncAttributeMaxDynamicSharedMemorySize, smem_tail);

    init_kernel<<<(Bq*GSZ)/256, 256>>>();
    gmatln_kernel<<<dim3(NCH, Bq), 256, smem_gmatln>>>(emb1, emb2, ln1_g, ln1_b, lnA_g, lnA_b);
    smatT_kernel<<<dim3(Bq*Hh, 4), 256, smem_smatT>>>(Wq, Wk);
    pmatM_kernel<<<dim3(Bq*Hh, 4), 256, smem_pmatM>>>(Wv, Wout);
    tail_kernel<<<dim3(NCH, Bq), 256, smem_tail>>>(emb1, fc1_w, fc2_w, fc1_b, fc2_b, ffn_g, ffn_b, out);
}